// round 5
// baseline (speedup 1.0000x reference)
#include <cuda_runtime.h>
#include <cuda_fp16.h>
#include <cstdint>

// ---------------------------------------------------------------------------
// Problem constants
// ---------------------------------------------------------------------------
#define NPTS   524288
#define LVLS   16
#define TSIZE  524288u
#define TMASK  (TSIZE - 1u)

__constant__ float c_res[LVLS] = {
    16.f, 24.f, 36.f, 54.f, 81.f, 121.f, 182.f, 273.f,
    410.f, 615.f, 922.f, 1383.f, 2075.f, 3113.f, 4670.f, 7006.f
};

// ---------------------------------------------------------------------------
// Scratch (device globals; no runtime allocation)
// ---------------------------------------------------------------------------
__device__ __align__(16) __half g_enc_s_hi[(size_t)NPTS * 32];
__device__ __align__(16) __half g_enc_s_lo[(size_t)NPTS * 32];
__device__ __align__(16) __half g_enc_d_hi[(size_t)NPTS * 32];
__device__ __align__(16) __half g_enc_d_lo[(size_t)NPTS * 32];
__device__ __align__(16) __half g_feat_hi [(size_t)NPTS * 128];
__device__ __align__(16) __half g_feat_lo [(size_t)NPTS * 128];

// Pre-split weight blobs (hi plane, lo plane at +rows*stride), stride 72/136
#define WB_IN   0
#define WB_H0   4608
#define WB_H1   13824
#define WB_H2   23040
#define WB_OUT  32256
#define WB_TOT  41472
__device__ __align__(16) __half g_wS[WB_TOT];
__device__ __align__(16) __half g_wD[WB_TOT];
#define H1_IN   0
#define H1_H    18432
#define H1_OUT  27648
#define H1_TOT  45056
__device__ __align__(16) __half g_wH1[H1_TOT];
#define H2_IN   0
#define H2_H    18432
#define H2_TOT  27648
__device__ __align__(16) __half g_wH2[H2_TOT];

// ---------------------------------------------------------------------------
__device__ __forceinline__ void split2(float x, __half& h, __half& l) {
    h = __float2half_rn(x);
    l = __float2half_rn(x - __half2float(h));
}

__device__ __forceinline__ void conv_w(__half* dst, const float* __restrict__ src,
                                       int K, int N, int ws, int t0, int nt)
{
    const int tot = K * N / 2;
    const int pl  = K * ws;
    const float2* s2 = (const float2*)src;
    for (int i = t0; i < tot; i += nt) {
        int r = (2 * i) / N, c = (2 * i) % N;
        float2 v = s2[i];
        __half hx, lx, hy, ly;
        split2(v.x, hx, lx);
        split2(v.y, hy, ly);
        *(__half2*)(dst + r * ws + c)      = __halves2half2(hx, hy);
        *(__half2*)(dst + r * ws + pl + c) = __halves2half2(lx, ly);
    }
}

__global__ void __launch_bounds__(256)
prep_weights(const float* __restrict__ ws_in, const float* __restrict__ ws_hid,
             const float* __restrict__ ws_out,
             const float* __restrict__ wd_in, const float* __restrict__ wd_hid,
             const float* __restrict__ wd_out,
             const float* __restrict__ w1_in, const float* __restrict__ w1_hid,
             const float* __restrict__ w1_out,
             const float* __restrict__ w2_in, const float* __restrict__ w2_hid)
{
    const int t0 = blockIdx.x * 256 + threadIdx.x;
    const int nt = gridDim.x * 256;
    conv_w(g_wS + WB_IN,  ws_in,         32, 64, 72, t0, nt);
    conv_w(g_wS + WB_H0,  ws_hid + 0,    64, 64, 72, t0, nt);
    conv_w(g_wS + WB_H1,  ws_hid + 4096, 64, 64, 72, t0, nt);
    conv_w(g_wS + WB_H2,  ws_hid + 8192, 64, 64, 72, t0, nt);
    conv_w(g_wS + WB_OUT, ws_out,        64, 64, 72, t0, nt);
    conv_w(g_wD + WB_IN,  wd_in,         32, 64, 72, t0, nt);
    conv_w(g_wD + WB_H0,  wd_hid + 0,    64, 64, 72, t0, nt);
    conv_w(g_wD + WB_H1,  wd_hid + 4096, 64, 64, 72, t0, nt);
    conv_w(g_wD + WB_H2,  wd_hid + 8192, 64, 64, 72, t0, nt);
    conv_w(g_wD + WB_OUT, wd_out,        64, 64, 72, t0, nt);
    conv_w(g_wH1 + H1_IN,  w1_in,  128, 64,  72,  t0, nt);
    conv_w(g_wH1 + H1_H,   w1_hid, 64,  64,  72,  t0, nt);
    conv_w(g_wH1 + H1_OUT, w1_out, 64,  128, 136, t0, nt);
    conv_w(g_wH2 + H2_IN,  w2_in,  128, 64,  72,  t0, nt);
    conv_w(g_wH2 + H2_H,   w2_hid, 64,  64,  72,  t0, nt);
}

// ---------------------------------------------------------------------------
// Hash-grid encode, level-chunked: each thread handles LV levels of one point.
// D=3: 4 levels/thread (chunks=4); D=4: 2 levels/thread (chunks=8).
// chunk = tid / PPB is warp-uniform.
// ---------------------------------------------------------------------------
template <int D, int WHICH>
__global__ void __launch_bounds__(256)
encode_kernel(const float* __restrict__ x,
              const float* __restrict__ tptr,
              const float* __restrict__ table)
{
    constexpr int CH  = (D == 3) ? 4 : 8;    // chunks per point
    constexpr int LV  = LVLS / CH;           // levels per thread
    constexpr int PPB = 256 / CH;            // points per block

    const int tid   = threadIdx.x;
    const int n     = blockIdx.x * PPB + (tid & (PPB - 1));
    const int chunk = tid / PPB;             // warp-uniform
    const int l0    = chunk * LV;

    float p[4];
    p[0] = x[3 * n + 0];
    p[1] = x[3 * n + 1];
    p[2] = x[3 * n + 2];
    if (D == 4) p[3] = __ldg(tptr);

    __half2 ehi[LV], elo[LV];

    #pragma unroll
    for (int li = 0; li < LV; li++) {
        const int   l   = l0 + li;
        const float res = c_res[l];
        uint32_t h[4][2];
        float    w[4][2];
        #pragma unroll
        for (int d = 0; d < D; d++) {
            const uint32_t pr = (d == 0) ? 1u
                              : (d == 1) ? 2654435761u
                              : (d == 2) ? 805459861u
                                         : 3674653429u;
            float pos = p[d] * res;
            float p0f = floorf(pos);
            float fr  = pos - p0f;
            uint32_t p0 = (uint32_t)p0f;
            h[d][0] = p0 * pr;
            h[d][1] = (p0 + 1u) * pr;
            w[d][0] = 1.f - fr;
            w[d][1] = fr;
        }

        const float2* tl = (const float2*)table + (size_t)l * TSIZE;
        float f0 = 0.f, f1 = 0.f;
        #pragma unroll
        for (int c = 0; c < (1 << D); c++) {
            uint32_t hh = h[0][c & 1] ^ h[1][(c >> 1) & 1] ^ h[2][(c >> 2) & 1];
            float    ww = w[0][c & 1] * w[1][(c >> 1) & 1] * w[2][(c >> 2) & 1];
            if (D == 4) {
                hh ^= h[3][(c >> 3) & 1];
                ww *= w[3][(c >> 3) & 1];
            }
            float2 f = __ldg(tl + (hh & TMASK));
            f0 = fmaf(ww, f.x, f0);
            f1 = fmaf(ww, f.y, f1);
        }
        __half h0v, l0v, h1v, l1v;
        split2(f0, h0v, l0v);
        split2(f1, h1v, l1v);
        ehi[li] = __halves2half2(h0v, h1v);
        elo[li] = __halves2half2(l0v, l1v);
    }

    __half* dh = (WHICH == 0 ? g_enc_s_hi : g_enc_d_hi) + (size_t)n * 32 + l0 * 2;
    __half* dl = (WHICH == 0 ? g_enc_s_lo : g_enc_d_lo) + (size_t)n * 32 + l0 * 2;
    if (LV == 4) {
        *(uint4*)dh = *(const uint4*)ehi;
        *(uint4*)dl = *(const uint4*)elo;
    } else {
        *(uint2*)dh = *(const uint2*)ehi;
        *(uint2*)dl = *(const uint2*)elo;
    }
}

// ---------------------------------------------------------------------------
// Tensor-core primitives
// ---------------------------------------------------------------------------
__device__ __forceinline__ uint32_t smem_u32(const void* p) {
    return (uint32_t)__cvta_generic_to_shared(p);
}

__device__ __forceinline__ void ldsm_x4(uint32_t& r0, uint32_t& r1,
                                        uint32_t& r2, uint32_t& r3, uint32_t a) {
    asm volatile("ldmatrix.sync.aligned.m8n8.x4.shared.b16 {%0,%1,%2,%3}, [%4];"
                 : "=r"(r0), "=r"(r1), "=r"(r2), "=r"(r3) : "r"(a));
}

__device__ __forceinline__ void ldsm_x4_t(uint32_t& r0, uint32_t& r1,
                                          uint32_t& r2, uint32_t& r3, uint32_t a) {
    asm volatile("ldmatrix.sync.aligned.m8n8.x4.trans.shared.b16 {%0,%1,%2,%3}, [%4];"
                 : "=r"(r0), "=r"(r1), "=r"(r2), "=r"(r3) : "r"(a));
}

__device__ __forceinline__ void mma16816(float* c, const uint32_t* a,
                                         uint32_t b0, uint32_t b1) {
    asm volatile(
        "mma.sync.aligned.m16n8k16.row.col.f32.f16.f16.f32 "
        "{%0,%1,%2,%3}, {%4,%5,%6,%7}, {%8,%9}, {%0,%1,%2,%3};"
        : "+f"(c[0]), "+f"(c[1]), "+f"(c[2]), "+f"(c[3])
        : "r"(a[0]), "r"(a[1]), "r"(a[2]), "r"(a[3]), "r"(b0), "r"(b1));
}

// ---------------------------------------------------------------------------
// Split-fp16 warp GEMM, 2 M-tiles (32 rows/warp), in-place-safe.
// ---------------------------------------------------------------------------
template <int KT, int NT, bool RELU, bool BLEND>
__device__ __forceinline__ void gemm2(const __half* A, int sa, int apl,
                                      const __half* W, int ws, int wpl, int noff,
                                      __half* Bo, int sb, int bpl,
                                      float alpha, float beta)
{
    asm volatile("" ::: "memory");
    const int lane = threadIdx.x & 31;
    float acc[2][NT][4];
    #pragma unroll
    for (int m = 0; m < 2; m++)
        #pragma unroll
        for (int t = 0; t < NT; t++)
            #pragma unroll
            for (int j = 0; j < 4; j++) acc[m][t][j] = 0.f;

    #pragma unroll
    for (int kk = 0; kk < KT; kk++) {
        uint32_t ah[2][4], al[2][4];
        #pragma unroll
        for (int m = 0; m < 2; m++) {
            const __half* ap = A + (m * 16 + (lane & 15)) * sa + kk * 16
                             + ((lane >> 4) << 3);
            ldsm_x4(ah[m][0], ah[m][1], ah[m][2], ah[m][3], smem_u32(ap));
            ldsm_x4(al[m][0], al[m][1], al[m][2], al[m][3], smem_u32(ap + apl));
        }
        #pragma unroll
        for (int nb = 0; nb < NT / 2; nb++) {
            const __half* wp = W + (kk * 16 + (lane & 7) + ((lane >> 3) & 1) * 8) * ws
                             + noff + nb * 16 + ((lane >> 4) << 3);
            uint32_t bh0, bh1, bh2, bh3, bl0, bl1, bl2, bl3;
            ldsm_x4_t(bh0, bh1, bh2, bh3, smem_u32(wp));
            ldsm_x4_t(bl0, bl1, bl2, bl3, smem_u32(wp + wpl));
            #pragma unroll
            for (int m = 0; m < 2; m++) {
                mma16816(acc[m][2 * nb + 0], ah[m], bh0, bh1);
                mma16816(acc[m][2 * nb + 0], ah[m], bl0, bl1);
                mma16816(acc[m][2 * nb + 0], al[m], bh0, bh1);
                mma16816(acc[m][2 * nb + 1], ah[m], bh2, bh3);
                mma16816(acc[m][2 * nb + 1], ah[m], bl2, bl3);
                mma16816(acc[m][2 * nb + 1], al[m], bh2, bh3);
            }
        }
    }

    __syncwarp();
    #pragma unroll
    for (int m = 0; m < 2; m++) {
        const int r0 = m * 16 + (lane >> 2);
        #pragma unroll
        for (int t = 0; t < NT; t++) {
            const int c0 = noff + t * 8 + (lane & 3) * 2;
            float v[4] = { acc[m][t][0], acc[m][t][1], acc[m][t][2], acc[m][t][3] };
            if (RELU) {
                #pragma unroll
                for (int j = 0; j < 4; j++) v[j] = fmaxf(v[j], 0.f);
            }
            if (BLEND) {
                const int rr[4] = { r0, r0, r0 + 8, r0 + 8 };
                const int cc[4] = { c0, c0 + 1, c0, c0 + 1 };
                #pragma unroll
                for (int j = 0; j < 4; j++) {
                    float fv = __half2float(Bo[rr[j] * sb + cc[j]])
                             + __half2float(Bo[rr[j] * sb + bpl + cc[j]]);
                    v[j] = v[j] * alpha + beta * fv;
                }
            }
            __half h0, l0, h1, l1, h2, l2, h3, l3;
            split2(v[0], h0, l0); split2(v[1], h1, l1);
            split2(v[2], h2, l2); split2(v[3], h3, l3);
            *(__half2*)(Bo + r0 * sb + c0)             = __halves2half2(h0, h1);
            *(__half2*)(Bo + r0 * sb + bpl + c0)       = __halves2half2(l0, l1);
            *(__half2*)(Bo + (r0 + 8) * sb + c0)       = __halves2half2(h2, h3);
            *(__half2*)(Bo + (r0 + 8) * sb + bpl + c0) = __halves2half2(l2, l3);
        }
    }
    __syncwarp();
    asm volatile("" ::: "memory");
}

// ---------------------------------------------------------------------------
// Branch MLP: 256 threads = 8 warps x 32 pts = 256 pts/block.
// ---------------------------------------------------------------------------
#define M_XPL   (256 * 72)
#define M_SMW   (256 * 72 * 2)
#define MLP64_SMEM ((M_SMW + WB_TOT) * 2)

template <int WHICH>
__global__ void __launch_bounds__(256, 1)
mlp64_tc()
{
    extern __shared__ __align__(16) __half sm[];
    const int tid = threadIdx.x;
    const size_t blockbase = (size_t)blockIdx.x * 256;

    {
        const uint4* src = (const uint4*)(WHICH == 0 ? g_wS : g_wD);
        uint4* dst = (uint4*)(sm + M_SMW);
        #pragma unroll 4
        for (int i = tid; i < WB_TOT / 8; i += 256) dst[i] = src[i];
    }
    {
        const uint4* sh = (const uint4*)((WHICH == 0 ? g_enc_s_hi : g_enc_d_hi)
                                         + blockbase * 32);
        const uint4* sl = (const uint4*)((WHICH == 0 ? g_enc_s_lo : g_enc_d_lo)
                                         + blockbase * 32);
        for (int i = tid; i < 256 * 4; i += 256) {
            int row = i >> 2, c = (i & 3) << 3;
            *(uint4*)(sm + row * 72 + c)         = sh[i];
            *(uint4*)(sm + M_XPL + row * 72 + c) = sl[i];
        }
    }
    __syncthreads();

    const int w = tid >> 5;
    __half* X = sm + w * 32 * 72;
    const __half* W = sm + M_SMW;

    gemm2<2, 8, true,  false>(X, 72, M_XPL, W + WB_IN,  72, 32 * 72, 0, X, 72, M_XPL, 0.f, 0.f);
    gemm2<4, 8, true,  false>(X, 72, M_XPL, W + WB_H0,  72, 64 * 72, 0, X, 72, M_XPL, 0.f, 0.f);
    gemm2<4, 8, true,  false>(X, 72, M_XPL, W + WB_H1,  72, 64 * 72, 0, X, 72, M_XPL, 0.f, 0.f);
    gemm2<4, 8, true,  false>(X, 72, M_XPL, W + WB_H2,  72, 64 * 72, 0, X, 72, M_XPL, 0.f, 0.f);
    gemm2<4, 8, false, false>(X, 72, M_XPL, W + WB_OUT, 72, 64 * 72, 0, X, 72, M_XPL, 0.f, 0.f);

    const int lane = tid & 31;
    for (int i = lane; i < 32 * 8; i += 32) {
        int row = i >> 3, c = (i & 7) << 3;
        size_t pt = blockbase + w * 32 + row;
        *(uint4*)(g_feat_hi + pt * 128 + WHICH * 64 + c) = *(const uint4*)(X + row * 72 + c);
        *(uint4*)(g_feat_lo + pt * 128 + WHICH * 64 + c) = *(const uint4*)(X + M_XPL + row * 72 + c);
    }
}

// ---------------------------------------------------------------------------
// head1: feat128 -> 64 -> 64 -> 128 (+blend fused); writes blended to g_feat
// ---------------------------------------------------------------------------
#define HD_FPL  (128 * 136)
#define HD_X    (128 * 136 * 2)
#define HD_XPL  (128 * 72)
#define HD_W    (HD_X + 128 * 72 * 2)
#define HEAD1_SMEM ((HD_W + H1_TOT) * 2)
#define HEAD2_SMEM ((HD_W + H2_TOT + 128) * 2)

__global__ void __launch_bounds__(128, 1)
head1_tc(const float* __restrict__ alpha_p)
{
    extern __shared__ __align__(16) __half sm[];
    const int tid = threadIdx.x;
    const size_t blockbase = (size_t)blockIdx.x * 128;

    {
        const uint4* src = (const uint4*)g_wH1;
        uint4* dst = (uint4*)(sm + HD_W);
        #pragma unroll 4
        for (int i = tid; i < H1_TOT / 8; i += 128) dst[i] = src[i];
    }
    {
        const uint4* fh = (const uint4*)(g_feat_hi + blockbase * 128);
        const uint4* fl = (const uint4*)(g_feat_lo + blockbase * 128);
        for (int i = tid; i < 128 * 16; i += 128) {
            int row = i >> 4, c = (i & 15) << 3;
            *(uint4*)(sm + row * 136 + c)          = fh[i];
            *(uint4*)(sm + HD_FPL + row * 136 + c) = fl[i];
        }
    }
    __syncthreads();

    const int w = tid >> 5;
    __half* F = sm + w * 32 * 136;
    __half* X = sm + HD_X + w * 32 * 72;
    const __half* W = sm + HD_W;

    const float alpha = __ldg(alpha_p);
    const float beta  = 1.f - alpha;

    gemm2<8, 8, true, false>(F, 136, HD_FPL, W + H1_IN, 72, 128 * 72, 0, X, 72, HD_XPL, 0.f, 0.f);
    gemm2<4, 8, true, false>(X, 72, HD_XPL,  W + H1_H,  72, 64 * 72,  0, X, 72, HD_XPL, 0.f, 0.f);
    gemm2<4, 8, false, true>(X, 72, HD_XPL, W + H1_OUT, 136, 64 * 136, 0,  F, 136, HD_FPL, alpha, beta);
    gemm2<4, 8, false, true>(X, 72, HD_XPL, W + H1_OUT, 136, 64 * 136, 64, F, 136, HD_FPL, alpha, beta);

    const int lane = tid & 31;
    for (int i = lane; i < 32 * 16; i += 32) {
        int row = i >> 4, c = (i & 15) << 3;
        size_t pt = blockbase + w * 32 + row;
        *(uint4*)(g_feat_hi + pt * 128 + c) = *(const uint4*)(F + row * 136 + c);
        *(uint4*)(g_feat_lo + pt * 128 + c) = *(const uint4*)(F + HD_FPL + row * 136 + c);
    }
}

// ---------------------------------------------------------------------------
// head2: blended128 -> 64 -> 64 -> 1
// ---------------------------------------------------------------------------
__global__ void __launch_bounds__(128, 1)
head2_tc(const float* __restrict__ w2_out, float* __restrict__ out)
{
    extern __shared__ __align__(16) __half sm[];
    const int tid = threadIdx.x;
    const size_t blockbase = (size_t)blockIdx.x * 128;
    float* wo = (float*)(sm + HD_W + H2_TOT);

    {
        const uint4* src = (const uint4*)g_wH2;
        uint4* dst = (uint4*)(sm + HD_W);
        #pragma unroll 4
        for (int i = tid; i < H2_TOT / 8; i += 128) dst[i] = src[i];
        for (int i = tid; i < 64; i += 128) wo[i] = w2_out[i];
    }
    {
        const uint4* fh = (const uint4*)(g_feat_hi + blockbase * 128);
        const uint4* fl = (const uint4*)(g_feat_lo + blockbase * 128);
        for (int i = tid; i < 128 * 16; i += 128) {
            int row = i >> 4, c = (i & 15) << 3;
            *(uint4*)(sm + row * 136 + c)          = fh[i];
            *(uint4*)(sm + HD_FPL + row * 136 + c) = fl[i];
        }
    }
    __syncthreads();

    const int w = tid >> 5;
    const int lane = tid & 31;
    __half* F = sm + w * 32 * 136;
    __half* X = sm + HD_X + w * 32 * 72;
    const __half* W = sm + HD_W;

    gemm2<8, 8, true, false>(F, 136, HD_FPL, W + H2_IN, 72, 128 * 72, 0, X, 72, HD_XPL, 0.f, 0.f);
    gemm2<4, 8, true, false>(X, 72, HD_XPL,  W + H2_H,  72, 64 * 72,  0, X, 72, HD_XPL, 0.f, 0.f);

    float acc = 0.f;
    #pragma unroll
    for (int k = 0; k < 64; k++) {
        float v = __half2float(X[lane * 72 + k])
                + __half2float(X[HD_XPL + lane * 72 + k]);
        acc = fmaf(v, wo[k], acc);
    }
    out[blockbase + w * 32 + lane] = acc;
}

// ---------------------------------------------------------------------------
// Launch: fork mlp64_s onto a second stream so it overlaps encode_d.
// ---------------------------------------------------------------------------
extern "C" void kernel_launch(void* const* d_in, const int* in_sizes, int n_in,
                              void* d_out, int out_size)
{
    const float* x       = (const float*)d_in[0];
    const float* t       = (const float*)d_in[1];
    const float* alpha   = (const float*)d_in[2];
    const float* table_s = (const float*)d_in[3];
    const float* ws_in   = (const float*)d_in[4];
    const float* ws_hid  = (const float*)d_in[5];
    const float* ws_out  = (const float*)d_in[6];
    const float* table_d = (const float*)d_in[7];
    const float* wd_in   = (const float*)d_in[8];
    const float* wd_hid  = (const float*)d_in[9];
    const float* wd_out  = (const float*)d_in[10];
    const float* w1_in   = (const float*)d_in[11];
    const float* w1_hid  = (const float*)d_in[12];
    const float* w1_out  = (const float*)d_in[13];
    const float* w2_in   = (const float*)d_in[14];
    const float* w2_hid  = (const float*)d_in[15];
    const float* w2_out  = (const float*)d_in[16];
    float* out = (float*)d_out;

    static cudaStream_t s1 = nullptr;
    static cudaEvent_t  eS = nullptr, eM = nullptr;
    if (s1 == nullptr) {
        cudaStreamCreateWithFlags(&s1, cudaStreamNonBlocking);
        cudaEventCreateWithFlags(&eS, cudaEventDisableTiming);
        cudaEventCreateWithFlags(&eM, cudaEventDisableTiming);
    }

    cudaFuncSetAttribute(mlp64_tc<0>, cudaFuncAttributeMaxDynamicSharedMemorySize, MLP64_SMEM);
    cudaFuncSetAttribute(mlp64_tc<1>, cudaFuncAttributeMaxDynamicSharedMemorySize, MLP64_SMEM);
    cudaFuncSetAttribute(head1_tc,    cudaFuncAttributeMaxDynamicSharedMemorySize, HEAD1_SMEM);
    cudaFuncSetAttribute(head2_tc,    cudaFuncAttributeMaxDynamicSharedMemorySize, HEAD2_SMEM);

    const int nblkE3  = NPTS * 4 / 256;   // d=3: 4 chunks/pt
    const int nblkE4  = NPTS * 8 / 256;   // d=4: 8 chunks/pt
    const int nblkMLP = NPTS / 256;
    const int nblkHD  = NPTS / 128;

    prep_weights<<<64, 256>>>(ws_in, ws_hid, ws_out, wd_in, wd_hid, wd_out,
                              w1_in, w1_hid, w1_out, w2_in, w2_hid);

    encode_kernel<3, 0><<<nblkE3, 256>>>(x, nullptr, table_s);
    cudaEventRecord(eS, 0);

    // fork: static-branch MLP runs concurrent with the dynamic encode
    cudaStreamWaitEvent(s1, eS, 0);
    mlp64_tc<0><<<nblkMLP, 256, MLP64_SMEM, s1>>>();
    cudaEventRecord(eM, s1);

    encode_kernel<4, 1><<<nblkE4, 256>>>(x, t, table_d);
    mlp64_tc<1><<<nblkMLP, 256, MLP64_SMEM>>>();

    // join before the head consumes both feature halves
    cudaStreamWaitEvent(0, eM, 0);
    head1_tc<<<nblkHD, 128, HEAD1_SMEM>>>(alpha);
    head2_tc<<<nblkHD, 128, HEAD2_SMEM>>>(w2_out, out);
}

// round 6
// speedup vs baseline: 1.0228x; 1.0228x over previous
#include <cuda_runtime.h>
#include <cuda_fp16.h>
#include <cstdint>

// ---------------------------------------------------------------------------
// Problem constants
// ---------------------------------------------------------------------------
#define NPTS   524288
#define LVLS   16
#define TSIZE  524288u
#define TMASK  (TSIZE - 1u)

__constant__ float c_res[LVLS] = {
    16.f, 24.f, 36.f, 54.f, 81.f, 121.f, 182.f, 273.f,
    410.f, 615.f, 922.f, 1383.f, 2075.f, 3113.f, 4670.f, 7006.f
};

// ---------------------------------------------------------------------------
// Scratch (device globals; no runtime allocation)
// ---------------------------------------------------------------------------
__device__ __align__(16) __half g_enc_s_hi[(size_t)NPTS * 32];
__device__ __align__(16) __half g_enc_s_lo[(size_t)NPTS * 32];
__device__ __align__(16) __half g_enc_d_hi[(size_t)NPTS * 32];
__device__ __align__(16) __half g_enc_d_lo[(size_t)NPTS * 32];
__device__ __align__(16) __half g_feat_hi [(size_t)NPTS * 128];
__device__ __align__(16) __half g_feat_lo [(size_t)NPTS * 128];

// Pre-split weight blobs (hi plane, lo plane at +rows*stride), stride 72/136
#define WB_IN   0
#define WB_H0   4608
#define WB_H1   13824
#define WB_H2   23040
#define WB_OUT  32256
#define WB_TOT  41472
__device__ __align__(16) __half g_wS[WB_TOT];
__device__ __align__(16) __half g_wD[WB_TOT];
#define H1_IN   0
#define H1_H    18432
#define H1_OUT  27648
#define H1_TOT  45056
__device__ __align__(16) __half g_wH1[H1_TOT];
#define H2_IN   0
#define H2_H    18432
#define H2_TOT  27648
__device__ __align__(16) __half g_wH2[H2_TOT];

// ---------------------------------------------------------------------------
__device__ __forceinline__ void split2(float x, __half& h, __half& l) {
    h = __float2half_rn(x);
    l = __float2half_rn(x - __half2float(h));
}

__device__ __forceinline__ void conv_w(__half* dst, const float* __restrict__ src,
                                       int K, int N, int ws, int t0, int nt)
{
    const int tot = K * N / 2;
    const int pl  = K * ws;
    const float2* s2 = (const float2*)src;
    for (int i = t0; i < tot; i += nt) {
        int r = (2 * i) / N, c = (2 * i) % N;
        float2 v = s2[i];
        __half hx, lx, hy, ly;
        split2(v.x, hx, lx);
        split2(v.y, hy, ly);
        *(__half2*)(dst + r * ws + c)      = __halves2half2(hx, hy);
        *(__half2*)(dst + r * ws + pl + c) = __halves2half2(lx, ly);
    }
}

__global__ void __launch_bounds__(256)
prep_weights(const float* __restrict__ ws_in, const float* __restrict__ ws_hid,
             const float* __restrict__ ws_out,
             const float* __restrict__ wd_in, const float* __restrict__ wd_hid,
             const float* __restrict__ wd_out,
             const float* __restrict__ w1_in, const float* __restrict__ w1_hid,
             const float* __restrict__ w1_out,
             const float* __restrict__ w2_in, const float* __restrict__ w2_hid)
{
    const int t0 = blockIdx.x * 256 + threadIdx.x;
    const int nt = gridDim.x * 256;
    conv_w(g_wS + WB_IN,  ws_in,         32, 64, 72, t0, nt);
    conv_w(g_wS + WB_H0,  ws_hid + 0,    64, 64, 72, t0, nt);
    conv_w(g_wS + WB_H1,  ws_hid + 4096, 64, 64, 72, t0, nt);
    conv_w(g_wS + WB_H2,  ws_hid + 8192, 64, 64, 72, t0, nt);
    conv_w(g_wS + WB_OUT, ws_out,        64, 64, 72, t0, nt);
    conv_w(g_wD + WB_IN,  wd_in,         32, 64, 72, t0, nt);
    conv_w(g_wD + WB_H0,  wd_hid + 0,    64, 64, 72, t0, nt);
    conv_w(g_wD + WB_H1,  wd_hid + 4096, 64, 64, 72, t0, nt);
    conv_w(g_wD + WB_H2,  wd_hid + 8192, 64, 64, 72, t0, nt);
    conv_w(g_wD + WB_OUT, wd_out,        64, 64, 72, t0, nt);
    conv_w(g_wH1 + H1_IN,  w1_in,  128, 64,  72,  t0, nt);
    conv_w(g_wH1 + H1_H,   w1_hid, 64,  64,  72,  t0, nt);
    conv_w(g_wH1 + H1_OUT, w1_out, 64,  128, 136, t0, nt);
    conv_w(g_wH2 + H2_IN,  w2_in,  128, 64,  72,  t0, nt);
    conv_w(g_wH2 + H2_H,   w2_hid, 64,  64,  72,  t0, nt);
}

// ---------------------------------------------------------------------------
// Hash-grid encode, level-chunked: each thread handles LV levels of one point.
// D=3: 4 levels/thread (chunks=4); D=4: 2 levels/thread (chunks=8).
// chunk = tid / PPB is warp-uniform.
// ---------------------------------------------------------------------------
template <int D, int WHICH>
__global__ void __launch_bounds__(256)
encode_kernel(const float* __restrict__ x,
              const float* __restrict__ tptr,
              const float* __restrict__ table)
{
    constexpr int CH  = (D == 3) ? 4 : 8;    // chunks per point
    constexpr int LV  = LVLS / CH;           // levels per thread
    constexpr int PPB = 256 / CH;            // points per block

    const int tid   = threadIdx.x;
    const int n     = blockIdx.x * PPB + (tid & (PPB - 1));
    const int chunk = tid / PPB;             // warp-uniform
    const int l0    = chunk * LV;

    float p[4];
    p[0] = x[3 * n + 0];
    p[1] = x[3 * n + 1];
    p[2] = x[3 * n + 2];
    if (D == 4) p[3] = __ldg(tptr);

    __half2 ehi[LV], elo[LV];

    #pragma unroll
    for (int li = 0; li < LV; li++) {
        const int   l   = l0 + li;
        const float res = c_res[l];
        uint32_t h[4][2];
        float    w[4][2];
        #pragma unroll
        for (int d = 0; d < D; d++) {
            const uint32_t pr = (d == 0) ? 1u
                              : (d == 1) ? 2654435761u
                              : (d == 2) ? 805459861u
                                         : 3674653429u;
            float pos = p[d] * res;
            float p0f = floorf(pos);
            float fr  = pos - p0f;
            uint32_t p0 = (uint32_t)p0f;
            h[d][0] = p0 * pr;
            h[d][1] = (p0 + 1u) * pr;
            w[d][0] = 1.f - fr;
            w[d][1] = fr;
        }

        const float2* tl = (const float2*)table + (size_t)l * TSIZE;
        float f0 = 0.f, f1 = 0.f;
        #pragma unroll
        for (int c = 0; c < (1 << D); c++) {
            uint32_t hh = h[0][c & 1] ^ h[1][(c >> 1) & 1] ^ h[2][(c >> 2) & 1];
            float    ww = w[0][c & 1] * w[1][(c >> 1) & 1] * w[2][(c >> 2) & 1];
            if (D == 4) {
                hh ^= h[3][(c >> 3) & 1];
                ww *= w[3][(c >> 3) & 1];
            }
            float2 f = __ldg(tl + (hh & TMASK));
            f0 = fmaf(ww, f.x, f0);
            f1 = fmaf(ww, f.y, f1);
        }
        __half h0v, l0v, h1v, l1v;
        split2(f0, h0v, l0v);
        split2(f1, h1v, l1v);
        ehi[li] = __halves2half2(h0v, h1v);
        elo[li] = __halves2half2(l0v, l1v);
    }

    __half* dh = (WHICH == 0 ? g_enc_s_hi : g_enc_d_hi) + (size_t)n * 32 + l0 * 2;
    __half* dl = (WHICH == 0 ? g_enc_s_lo : g_enc_d_lo) + (size_t)n * 32 + l0 * 2;
    if (LV == 4) {
        *(uint4*)dh = *(const uint4*)ehi;
        *(uint4*)dl = *(const uint4*)elo;
    } else {
        *(uint2*)dh = *(const uint2*)ehi;
        *(uint2*)dl = *(const uint2*)elo;
    }
}

// ---------------------------------------------------------------------------
// Tensor-core primitives
// ---------------------------------------------------------------------------
__device__ __forceinline__ uint32_t smem_u32(const void* p) {
    return (uint32_t)__cvta_generic_to_shared(p);
}

__device__ __forceinline__ void ldsm_x4(uint32_t& r0, uint32_t& r1,
                                        uint32_t& r2, uint32_t& r3, uint32_t a) {
    asm volatile("ldmatrix.sync.aligned.m8n8.x4.shared.b16 {%0,%1,%2,%3}, [%4];"
                 : "=r"(r0), "=r"(r1), "=r"(r2), "=r"(r3) : "r"(a));
}

__device__ __forceinline__ void ldsm_x4_t(uint32_t& r0, uint32_t& r1,
                                          uint32_t& r2, uint32_t& r3, uint32_t a) {
    asm volatile("ldmatrix.sync.aligned.m8n8.x4.trans.shared.b16 {%0,%1,%2,%3}, [%4];"
                 : "=r"(r0), "=r"(r1), "=r"(r2), "=r"(r3) : "r"(a));
}

__device__ __forceinline__ void mma16816(float* c, const uint32_t* a,
                                         uint32_t b0, uint32_t b1) {
    asm volatile(
        "mma.sync.aligned.m16n8k16.row.col.f32.f16.f16.f32 "
        "{%0,%1,%2,%3}, {%4,%5,%6,%7}, {%8,%9}, {%0,%1,%2,%3};"
        : "+f"(c[0]), "+f"(c[1]), "+f"(c[2]), "+f"(c[3])
        : "r"(a[0]), "r"(a[1]), "r"(a[2]), "r"(a[3]), "r"(b0), "r"(b1));
}

// ---------------------------------------------------------------------------
// Split-fp16 warp GEMM, 2 M-tiles (32 rows/warp), in-place-safe.
// ---------------------------------------------------------------------------
template <int KT, int NT, bool RELU, bool BLEND>
__device__ __forceinline__ void gemm2(const __half* A, int sa, int apl,
                                      const __half* W, int ws, int wpl, int noff,
                                      __half* Bo, int sb, int bpl,
                                      float alpha, float beta)
{
    asm volatile("" ::: "memory");
    const int lane = threadIdx.x & 31;
    float acc[2][NT][4];
    #pragma unroll
    for (int m = 0; m < 2; m++)
        #pragma unroll
        for (int t = 0; t < NT; t++)
            #pragma unroll
            for (int j = 0; j < 4; j++) acc[m][t][j] = 0.f;

    #pragma unroll
    for (int kk = 0; kk < KT; kk++) {
        uint32_t ah[2][4], al[2][4];
        #pragma unroll
        for (int m = 0; m < 2; m++) {
            const __half* ap = A + (m * 16 + (lane & 15)) * sa + kk * 16
                             + ((lane >> 4) << 3);
            ldsm_x4(ah[m][0], ah[m][1], ah[m][2], ah[m][3], smem_u32(ap));
            ldsm_x4(al[m][0], al[m][1], al[m][2], al[m][3], smem_u32(ap + apl));
        }
        #pragma unroll
        for (int nb = 0; nb < NT / 2; nb++) {
            const __half* wp = W + (kk * 16 + (lane & 7) + ((lane >> 3) & 1) * 8) * ws
                             + noff + nb * 16 + ((lane >> 4) << 3);
            uint32_t bh0, bh1, bh2, bh3, bl0, bl1, bl2, bl3;
            ldsm_x4_t(bh0, bh1, bh2, bh3, smem_u32(wp));
            ldsm_x4_t(bl0, bl1, bl2, bl3, smem_u32(wp + wpl));
            #pragma unroll
            for (int m = 0; m < 2; m++) {
                mma16816(acc[m][2 * nb + 0], ah[m], bh0, bh1);
                mma16816(acc[m][2 * nb + 0], ah[m], bl0, bl1);
                mma16816(acc[m][2 * nb + 0], al[m], bh0, bh1);
                mma16816(acc[m][2 * nb + 1], ah[m], bh2, bh3);
                mma16816(acc[m][2 * nb + 1], ah[m], bl2, bl3);
                mma16816(acc[m][2 * nb + 1], al[m], bh2, bh3);
            }
        }
    }

    __syncwarp();
    #pragma unroll
    for (int m = 0; m < 2; m++) {
        const int r0 = m * 16 + (lane >> 2);
        #pragma unroll
        for (int t = 0; t < NT; t++) {
            const int c0 = noff + t * 8 + (lane & 3) * 2;
            float v[4] = { acc[m][t][0], acc[m][t][1], acc[m][t][2], acc[m][t][3] };
            if (RELU) {
                #pragma unroll
                for (int j = 0; j < 4; j++) v[j] = fmaxf(v[j], 0.f);
            }
            if (BLEND) {
                const int rr[4] = { r0, r0, r0 + 8, r0 + 8 };
                const int cc[4] = { c0, c0 + 1, c0, c0 + 1 };
                #pragma unroll
                for (int j = 0; j < 4; j++) {
                    float fv = __half2float(Bo[rr[j] * sb + cc[j]])
                             + __half2float(Bo[rr[j] * sb + bpl + cc[j]]);
                    v[j] = v[j] * alpha + beta * fv;
                }
            }
            __half h0, l0, h1, l1, h2, l2, h3, l3;
            split2(v[0], h0, l0); split2(v[1], h1, l1);
            split2(v[2], h2, l2); split2(v[3], h3, l3);
            *(__half2*)(Bo + r0 * sb + c0)             = __halves2half2(h0, h1);
            *(__half2*)(Bo + r0 * sb + bpl + c0)       = __halves2half2(l0, l1);
            *(__half2*)(Bo + (r0 + 8) * sb + c0)       = __halves2half2(h2, h3);
            *(__half2*)(Bo + (r0 + 8) * sb + bpl + c0) = __halves2half2(l2, l3);
        }
    }
    __syncwarp();
    asm volatile("" ::: "memory");
}

// ---------------------------------------------------------------------------
// Branch MLP: 256 threads = 8 warps x 32 pts = 256 pts/block.
// ---------------------------------------------------------------------------
#define M_XPL   (256 * 72)
#define M_SMW   (256 * 72 * 2)
#define MLP64_SMEM ((M_SMW + WB_TOT) * 2)

template <int WHICH>
__global__ void __launch_bounds__(256, 1)
mlp64_tc()
{
    extern __shared__ __align__(16) __half sm[];
    const int tid = threadIdx.x;
    const size_t blockbase = (size_t)blockIdx.x * 256;

    {
        const uint4* src = (const uint4*)(WHICH == 0 ? g_wS : g_wD);
        uint4* dst = (uint4*)(sm + M_SMW);
        #pragma unroll 4
        for (int i = tid; i < WB_TOT / 8; i += 256) dst[i] = src[i];
    }
    {
        const uint4* sh = (const uint4*)((WHICH == 0 ? g_enc_s_hi : g_enc_d_hi)
                                         + blockbase * 32);
        const uint4* sl = (const uint4*)((WHICH == 0 ? g_enc_s_lo : g_enc_d_lo)
                                         + blockbase * 32);
        for (int i = tid; i < 256 * 4; i += 256) {
            int row = i >> 2, c = (i & 3) << 3;
            *(uint4*)(sm + row * 72 + c)         = sh[i];
            *(uint4*)(sm + M_XPL + row * 72 + c) = sl[i];
        }
    }
    __syncthreads();

    const int w = tid >> 5;
    __half* X = sm + w * 32 * 72;
    const __half* W = sm + M_SMW;

    gemm2<2, 8, true,  false>(X, 72, M_XPL, W + WB_IN,  72, 32 * 72, 0, X, 72, M_XPL, 0.f, 0.f);
    gemm2<4, 8, true,  false>(X, 72, M_XPL, W + WB_H0,  72, 64 * 72, 0, X, 72, M_XPL, 0.f, 0.f);
    gemm2<4, 8, true,  false>(X, 72, M_XPL, W + WB_H1,  72, 64 * 72, 0, X, 72, M_XPL, 0.f, 0.f);
    gemm2<4, 8, true,  false>(X, 72, M_XPL, W + WB_H2,  72, 64 * 72, 0, X, 72, M_XPL, 0.f, 0.f);
    gemm2<4, 8, false, false>(X, 72, M_XPL, W + WB_OUT, 72, 64 * 72, 0, X, 72, M_XPL, 0.f, 0.f);

    const int lane = tid & 31;
    for (int i = lane; i < 32 * 8; i += 32) {
        int row = i >> 3, c = (i & 7) << 3;
        size_t pt = blockbase + w * 32 + row;
        *(uint4*)(g_feat_hi + pt * 128 + WHICH * 64 + c) = *(const uint4*)(X + row * 72 + c);
        *(uint4*)(g_feat_lo + pt * 128 + WHICH * 64 + c) = *(const uint4*)(X + M_XPL + row * 72 + c);
    }
}

// ---------------------------------------------------------------------------
// head1: feat128 -> 64 -> 64 -> 128 (+blend fused); writes blended to g_feat
// ---------------------------------------------------------------------------
#define HD_FPL  (128 * 136)
#define HD_X    (128 * 136 * 2)
#define HD_XPL  (128 * 72)
#define HD_W    (HD_X + 128 * 72 * 2)
#define HEAD1_SMEM ((HD_W + H1_TOT) * 2)
#define HEAD2_SMEM ((HD_W + H2_TOT + 128) * 2)

__global__ void __launch_bounds__(128, 1)
head1_tc(const float* __restrict__ alpha_p)
{
    extern __shared__ __align__(16) __half sm[];
    const int tid = threadIdx.x;
    const size_t blockbase = (size_t)blockIdx.x * 128;

    {
        const uint4* src = (const uint4*)g_wH1;
        uint4* dst = (uint4*)(sm + HD_W);
        #pragma unroll 4
        for (int i = tid; i < H1_TOT / 8; i += 128) dst[i] = src[i];
    }
    {
        const uint4* fh = (const uint4*)(g_feat_hi + blockbase * 128);
        const uint4* fl = (const uint4*)(g_feat_lo + blockbase * 128);
        for (int i = tid; i < 128 * 16; i += 128) {
            int row = i >> 4, c = (i & 15) << 3;
            *(uint4*)(sm + row * 136 + c)          = fh[i];
            *(uint4*)(sm + HD_FPL + row * 136 + c) = fl[i];
        }
    }
    __syncthreads();

    const int w = tid >> 5;
    __half* F = sm + w * 32 * 136;
    __half* X = sm + HD_X + w * 32 * 72;
    const __half* W = sm + HD_W;

    const float alpha = __ldg(alpha_p);
    const float beta  = 1.f - alpha;

    gemm2<8, 8, true, false>(F, 136, HD_FPL, W + H1_IN, 72, 128 * 72, 0, X, 72, HD_XPL, 0.f, 0.f);
    gemm2<4, 8, true, false>(X, 72, HD_XPL,  W + H1_H,  72, 64 * 72,  0, X, 72, HD_XPL, 0.f, 0.f);
    gemm2<4, 8, false, true>(X, 72, HD_XPL, W + H1_OUT, 136, 64 * 136, 0,  F, 136, HD_FPL, alpha, beta);
    gemm2<4, 8, false, true>(X, 72, HD_XPL, W + H1_OUT, 136, 64 * 136, 64, F, 136, HD_FPL, alpha, beta);

    const int lane = tid & 31;
    for (int i = lane; i < 32 * 16; i += 32) {
        int row = i >> 4, c = (i & 15) << 3;
        size_t pt = blockbase + w * 32 + row;
        *(uint4*)(g_feat_hi + pt * 128 + c) = *(const uint4*)(F + row * 136 + c);
        *(uint4*)(g_feat_lo + pt * 128 + c) = *(const uint4*)(F + HD_FPL + row * 136 + c);
    }
}

// ---------------------------------------------------------------------------
// head2: blended128 -> 64 -> 64 -> 1
// ---------------------------------------------------------------------------
__global__ void __launch_bounds__(128, 1)
head2_tc(const float* __restrict__ w2_out, float* __restrict__ out)
{
    extern __shared__ __align__(16) __half sm[];
    const int tid = threadIdx.x;
    const size_t blockbase = (size_t)blockIdx.x * 128;
    float* wo = (float*)(sm + HD_W + H2_TOT);

    {
        const uint4* src = (const uint4*)g_wH2;
        uint4* dst = (uint4*)(sm + HD_W);
        #pragma unroll 4
        for (int i = tid; i < H2_TOT / 8; i += 128) dst[i] = src[i];
        for (int i = tid; i < 64; i += 128) wo[i] = w2_out[i];
    }
    {
        const uint4* fh = (const uint4*)(g_feat_hi + blockbase * 128);
        const uint4* fl = (const uint4*)(g_feat_lo + blockbase * 128);
        for (int i = tid; i < 128 * 16; i += 128) {
            int row = i >> 4, c = (i & 15) << 3;
            *(uint4*)(sm + row * 136 + c)          = fh[i];
            *(uint4*)(sm + HD_FPL + row * 136 + c) = fl[i];
        }
    }
    __syncthreads();

    const int w = tid >> 5;
    const int lane = tid & 31;
    __half* F = sm + w * 32 * 136;
    __half* X = sm + HD_X + w * 32 * 72;
    const __half* W = sm + HD_W;

    gemm2<8, 8, true, false>(F, 136, HD_FPL, W + H2_IN, 72, 128 * 72, 0, X, 72, HD_XPL, 0.f, 0.f);
    gemm2<4, 8, true, false>(X, 72, HD_XPL,  W + H2_H,  72, 64 * 72,  0, X, 72, HD_XPL, 0.f, 0.f);

    float acc = 0.f;
    #pragma unroll
    for (int k = 0; k < 64; k++) {
        float v = __half2float(X[lane * 72 + k])
                + __half2float(X[HD_XPL + lane * 72 + k]);
        acc = fmaf(v, wo[k], acc);
    }
    out[blockbase + w * 32 + lane] = acc;
}

// ---------------------------------------------------------------------------
// Launch: strictly serial — overlapping L1-bound kernels regressed in R5.
// ---------------------------------------------------------------------------
extern "C" void kernel_launch(void* const* d_in, const int* in_sizes, int n_in,
                              void* d_out, int out_size)
{
    const float* x       = (const float*)d_in[0];
    const float* t       = (const float*)d_in[1];
    const float* alpha   = (const float*)d_in[2];
    const float* table_s = (const float*)d_in[3];
    const float* ws_in   = (const float*)d_in[4];
    const float* ws_hid  = (const float*)d_in[5];
    const float* ws_out  = (const float*)d_in[6];
    const float* table_d = (const float*)d_in[7];
    const float* wd_in   = (const float*)d_in[8];
    const float* wd_hid  = (const float*)d_in[9];
    const float* wd_out  = (const float*)d_in[10];
    const float* w1_in   = (const float*)d_in[11];
    const float* w1_hid  = (const float*)d_in[12];
    const float* w1_out  = (const float*)d_in[13];
    const float* w2_in   = (const float*)d_in[14];
    const float* w2_hid  = (const float*)d_in[15];
    const float* w2_out  = (const float*)d_in[16];
    float* out = (float*)d_out;

    cudaFuncSetAttribute(mlp64_tc<0>, cudaFuncAttributeMaxDynamicSharedMemorySize, MLP64_SMEM);
    cudaFuncSetAttribute(mlp64_tc<1>, cudaFuncAttributeMaxDynamicSharedMemorySize, MLP64_SMEM);
    cudaFuncSetAttribute(head1_tc,    cudaFuncAttributeMaxDynamicSharedMemorySize, HEAD1_SMEM);
    cudaFuncSetAttribute(head2_tc,    cudaFuncAttributeMaxDynamicSharedMemorySize, HEAD2_SMEM);

    const int nblkE3  = NPTS * 4 / 256;   // d=3: 4 chunks/pt
    const int nblkE4  = NPTS * 8 / 256;   // d=4: 8 chunks/pt
    const int nblkMLP = NPTS / 256;
    const int nblkHD  = NPTS / 128;

    prep_weights<<<64, 256>>>(ws_in, ws_hid, ws_out, wd_in, wd_hid, wd_out,
                              w1_in, w1_hid, w1_out, w2_in, w2_hid);

    encode_kernel<3, 0><<<nblkE3, 256>>>(x, nullptr, table_s);
    encode_kernel<4, 1><<<nblkE4, 256>>>(x, t, table_d);

    mlp64_tc<0><<<nblkMLP, 256, MLP64_SMEM>>>();
    mlp64_tc<1><<<nblkMLP, 256, MLP64_SMEM>>>();

    head1_tc<<<nblkHD, 128, HEAD1_SMEM>>>(alpha);
    head2_tc<<<nblkHD, 128, HEAD2_SMEM>>>(w2_out, out);
}

// round 7
// speedup vs baseline: 1.2397x; 1.2121x over previous
#include <cuda_runtime.h>
#include <cuda_fp16.h>
#include <cstdint>

// ---------------------------------------------------------------------------
// Problem constants
// ---------------------------------------------------------------------------
#define NPTS   524288
#define LVLS   16
#define TSIZE  524288u
#define TMASK  (TSIZE - 1u)

__constant__ float c_res[LVLS] = {
    16.f, 24.f, 36.f, 54.f, 81.f, 121.f, 182.f, 273.f,
    410.f, 615.f, 922.f, 1383.f, 2075.f, 3113.f, 4670.f, 7006.f
};

// ---------------------------------------------------------------------------
// Scratch (device globals; no runtime allocation)
// ---------------------------------------------------------------------------
__device__ __align__(16) __half g_enc_s_hi[(size_t)NPTS * 32];
__device__ __align__(16) __half g_enc_s_lo[(size_t)NPTS * 32];
__device__ __align__(16) __half g_enc_d_hi[(size_t)NPTS * 32];
__device__ __align__(16) __half g_enc_d_lo[(size_t)NPTS * 32];
__device__ __align__(16) __half g_feat_hi [(size_t)NPTS * 128];
__device__ __align__(16) __half g_feat_lo [(size_t)NPTS * 128];

// Pre-split weight blobs (hi plane, lo plane at +rows*stride), stride 72/136
#define WB_IN   0
#define WB_H0   4608
#define WB_H1   13824
#define WB_H2   23040
#define WB_OUT  32256
#define WB_TOT  41472
__device__ __align__(16) __half g_wS[WB_TOT];
__device__ __align__(16) __half g_wD[WB_TOT];
#define H1_IN   0
#define H1_H    18432
#define H1_OUT  27648
#define H1_TOT  45056
__device__ __align__(16) __half g_wH1[H1_TOT];
#define H2_IN   0
#define H2_H    18432
#define H2_TOT  27648
__device__ __align__(16) __half g_wH2[H2_TOT];

// ---------------------------------------------------------------------------
__device__ __forceinline__ void split2(float x, __half& h, __half& l) {
    h = __float2half_rn(x);
    l = __float2half_rn(x - __half2float(h));
}

__device__ __forceinline__ uint32_t pack2(__half a, __half b) {
    __half2 v = __halves2half2(a, b);
    return *reinterpret_cast<uint32_t*>(&v);
}

__device__ __forceinline__ void conv_w(__half* dst, const float* __restrict__ src,
                                       int K, int N, int ws, int t0, int nt)
{
    const int tot = K * N / 2;
    const int pl  = K * ws;
    const float2* s2 = (const float2*)src;
    for (int i = t0; i < tot; i += nt) {
        int r = (2 * i) / N, c = (2 * i) % N;
        float2 v = s2[i];
        __half hx, lx, hy, ly;
        split2(v.x, hx, lx);
        split2(v.y, hy, ly);
        *(__half2*)(dst + r * ws + c)      = __halves2half2(hx, hy);
        *(__half2*)(dst + r * ws + pl + c) = __halves2half2(lx, ly);
    }
}

__global__ void __launch_bounds__(256)
prep_weights(const float* __restrict__ ws_in, const float* __restrict__ ws_hid,
             const float* __restrict__ ws_out,
             const float* __restrict__ wd_in, const float* __restrict__ wd_hid,
             const float* __restrict__ wd_out,
             const float* __restrict__ w1_in, const float* __restrict__ w1_hid,
             const float* __restrict__ w1_out,
             const float* __restrict__ w2_in, const float* __restrict__ w2_hid)
{
    const int t0 = blockIdx.x * 256 + threadIdx.x;
    const int nt = gridDim.x * 256;
    conv_w(g_wS + WB_IN,  ws_in,         32, 64, 72, t0, nt);
    conv_w(g_wS + WB_H0,  ws_hid + 0,    64, 64, 72, t0, nt);
    conv_w(g_wS + WB_H1,  ws_hid + 4096, 64, 64, 72, t0, nt);
    conv_w(g_wS + WB_H2,  ws_hid + 8192, 64, 64, 72, t0, nt);
    conv_w(g_wS + WB_OUT, ws_out,        64, 64, 72, t0, nt);
    conv_w(g_wD + WB_IN,  wd_in,         32, 64, 72, t0, nt);
    conv_w(g_wD + WB_H0,  wd_hid + 0,    64, 64, 72, t0, nt);
    conv_w(g_wD + WB_H1,  wd_hid + 4096, 64, 64, 72, t0, nt);
    conv_w(g_wD + WB_H2,  wd_hid + 8192, 64, 64, 72, t0, nt);
    conv_w(g_wD + WB_OUT, wd_out,        64, 64, 72, t0, nt);
    conv_w(g_wH1 + H1_IN,  w1_in,  128, 64,  72,  t0, nt);
    conv_w(g_wH1 + H1_H,   w1_hid, 64,  64,  72,  t0, nt);
    conv_w(g_wH1 + H1_OUT, w1_out, 64,  128, 136, t0, nt);
    conv_w(g_wH2 + H2_IN,  w2_in,  128, 64,  72,  t0, nt);
    conv_w(g_wH2 + H2_H,   w2_hid, 64,  64,  72,  t0, nt);
}

// ---------------------------------------------------------------------------
// Hash-grid encode (R4 variant: one point per thread, all 16 levels).
// ---------------------------------------------------------------------------
template <int D, int WHICH>
__global__ void __launch_bounds__(256)
encode_kernel(const float* __restrict__ x,
              const float* __restrict__ tptr,
              const float* __restrict__ table)
{
    const int n = blockIdx.x * 256 + threadIdx.x;

    float p[4];
    p[0] = x[3 * n + 0];
    p[1] = x[3 * n + 1];
    p[2] = x[3 * n + 2];
    if (D == 4) p[3] = __ldg(tptr);

    __half2 ehi[16], elo[16];

    #pragma unroll
    for (int l = 0; l < LVLS; l++) {
        const float res = c_res[l];
        uint32_t h[4][2];
        float    w[4][2];
        #pragma unroll
        for (int d = 0; d < D; d++) {
            const uint32_t pr = (d == 0) ? 1u
                              : (d == 1) ? 2654435761u
                              : (d == 2) ? 805459861u
                                         : 3674653429u;
            float pos = p[d] * res;
            float p0f = floorf(pos);
            float fr  = pos - p0f;
            uint32_t p0 = (uint32_t)p0f;
            h[d][0] = p0 * pr;
            h[d][1] = (p0 + 1u) * pr;
            w[d][0] = 1.f - fr;
            w[d][1] = fr;
        }

        const float2* tl = (const float2*)table + (size_t)l * TSIZE;
        float f0 = 0.f, f1 = 0.f;
        #pragma unroll
        for (int c = 0; c < (1 << D); c++) {
            uint32_t hh = h[0][c & 1] ^ h[1][(c >> 1) & 1] ^ h[2][(c >> 2) & 1];
            float    ww = w[0][c & 1] * w[1][(c >> 1) & 1] * w[2][(c >> 2) & 1];
            if (D == 4) {
                hh ^= h[3][(c >> 3) & 1];
                ww *= w[3][(c >> 3) & 1];
            }
            float2 f = __ldg(tl + (hh & TMASK));
            f0 = fmaf(ww, f.x, f0);
            f1 = fmaf(ww, f.y, f1);
        }
        __half h0, l0, h1, l1;
        split2(f0, h0, l0);
        split2(f1, h1, l1);
        ehi[l] = __halves2half2(h0, h1);
        elo[l] = __halves2half2(l0, l1);
    }

    __half* dh = (WHICH == 0 ? g_enc_s_hi : g_enc_d_hi) + (size_t)n * 32;
    __half* dl = (WHICH == 0 ? g_enc_s_lo : g_enc_d_lo) + (size_t)n * 32;
    #pragma unroll
    for (int i = 0; i < 4; i++) ((uint4*)dh)[i] = ((const uint4*)ehi)[i];
    #pragma unroll
    for (int i = 0; i < 4; i++) ((uint4*)dl)[i] = ((const uint4*)elo)[i];
}

// ---------------------------------------------------------------------------
// Tensor-core primitives
// ---------------------------------------------------------------------------
__device__ __forceinline__ uint32_t smem_u32(const void* p) {
    return (uint32_t)__cvta_generic_to_shared(p);
}

__device__ __forceinline__ void ldsm_x4(uint32_t& r0, uint32_t& r1,
                                        uint32_t& r2, uint32_t& r3, uint32_t a) {
    asm volatile("ldmatrix.sync.aligned.m8n8.x4.shared.b16 {%0,%1,%2,%3}, [%4];"
                 : "=r"(r0), "=r"(r1), "=r"(r2), "=r"(r3) : "r"(a));
}

__device__ __forceinline__ void ldsm_x4_t(uint32_t& r0, uint32_t& r1,
                                          uint32_t& r2, uint32_t& r3, uint32_t a) {
    asm volatile("ldmatrix.sync.aligned.m8n8.x4.trans.shared.b16 {%0,%1,%2,%3}, [%4];"
                 : "=r"(r0), "=r"(r1), "=r"(r2), "=r"(r3) : "r"(a));
}

__device__ __forceinline__ void mma16816(float* c, const uint32_t* a,
                                         uint32_t b0, uint32_t b1) {
    asm volatile(
        "mma.sync.aligned.m16n8k16.row.col.f32.f16.f16.f32 "
        "{%0,%1,%2,%3}, {%4,%5,%6,%7}, {%8,%9}, {%0,%1,%2,%3};"
        : "+f"(c[0]), "+f"(c[1]), "+f"(c[2]), "+f"(c[3])
        : "r"(a[0]), "r"(a[1]), "r"(a[2]), "r"(a[3]), "r"(b0), "r"(b1));
}

// ---------------------------------------------------------------------------
// Register-resident split-fp16 layers.
// Warp state: Ah/Al[m][j][q] = A fragments (hi/lo) for 2 M-tiles x 4 k-tiles.
// Identity: C-fragments of n-tile pair {2j,2j+1} == A-fragments of k-tile j.
// ---------------------------------------------------------------------------
template <bool RELU>
__device__ __forceinline__ void convert_acc(float acc[2][8][4],
                                            uint32_t Ah[2][4][4],
                                            uint32_t Al[2][4][4])
{
    #pragma unroll
    for (int m = 0; m < 2; m++)
        #pragma unroll
        for (int j = 0; j < 4; j++)
            #pragma unroll
            for (int q = 0; q < 4; q++) {
                float v0 = acc[m][2 * j + (q >> 1)][(q & 1) * 2 + 0];
                float v1 = acc[m][2 * j + (q >> 1)][(q & 1) * 2 + 1];
                if (RELU) { v0 = fmaxf(v0, 0.f); v1 = fmaxf(v1, 0.f); }
                __half h0, l0, h1, l1;
                split2(v0, h0, l0);
                split2(v1, h1, l1);
                Ah[m][j][q] = pack2(h0, h1);
                Al[m][j][q] = pack2(l0, l1);
            }
}

// Layer with A already in registers: K = KT*16 -> N = 64 (in-place A update)
template <int KT, bool RELU>
__device__ __forceinline__ void layer_reg(uint32_t Ah[2][4][4],
                                          uint32_t Al[2][4][4],
                                          const __half* W, int ws, int wpl)
{
    const int lane = threadIdx.x & 31;
    float acc[2][8][4];
    #pragma unroll
    for (int m = 0; m < 2; m++)
        #pragma unroll
        for (int t = 0; t < 8; t++)
            #pragma unroll
            for (int j = 0; j < 4; j++) acc[m][t][j] = 0.f;

    #pragma unroll
    for (int kk = 0; kk < KT; kk++) {
        #pragma unroll
        for (int nb = 0; nb < 4; nb++) {
            const __half* wp = W + (kk * 16 + (lane & 7) + ((lane >> 3) & 1) * 8) * ws
                             + nb * 16 + ((lane >> 4) << 3);
            uint32_t bh0, bh1, bh2, bh3, bl0, bl1, bl2, bl3;
            ldsm_x4_t(bh0, bh1, bh2, bh3, smem_u32(wp));
            ldsm_x4_t(bl0, bl1, bl2, bl3, smem_u32(wp + wpl));
            #pragma unroll
            for (int m = 0; m < 2; m++) {
                mma16816(acc[m][2 * nb + 0], Ah[m][kk], bh0, bh1);
                mma16816(acc[m][2 * nb + 0], Ah[m][kk], bl0, bl1);
                mma16816(acc[m][2 * nb + 0], Al[m][kk], bh0, bh1);
                mma16816(acc[m][2 * nb + 1], Ah[m][kk], bh2, bh3);
                mma16816(acc[m][2 * nb + 1], Ah[m][kk], bl2, bl3);
                mma16816(acc[m][2 * nb + 1], Al[m][kk], bh2, bh3);
            }
        }
    }
    convert_acc<RELU>(acc, Ah, Al);
}

// Layer with A in smem (ldsm per k-tile): K = KT*16 -> N = 64 into registers
template <int KT, bool RELU>
__device__ __forceinline__ void layer_smemA(const __half* A, int sa, int apl,
                                            const __half* W, int ws, int wpl,
                                            uint32_t Ah[2][4][4],
                                            uint32_t Al[2][4][4])
{
    const int lane = threadIdx.x & 31;
    float acc[2][8][4];
    #pragma unroll
    for (int m = 0; m < 2; m++)
        #pragma unroll
        for (int t = 0; t < 8; t++)
            #pragma unroll
            for (int j = 0; j < 4; j++) acc[m][t][j] = 0.f;

    #pragma unroll
    for (int kk = 0; kk < KT; kk++) {
        uint32_t th[2][4], tl[2][4];
        #pragma unroll
        for (int m = 0; m < 2; m++) {
            const __half* ap = A + (m * 16 + (lane & 15)) * sa + kk * 16
                             + ((lane >> 4) << 3);
            ldsm_x4(th[m][0], th[m][1], th[m][2], th[m][3], smem_u32(ap));
            ldsm_x4(tl[m][0], tl[m][1], tl[m][2], tl[m][3], smem_u32(ap + apl));
        }
        #pragma unroll
        for (int nb = 0; nb < 4; nb++) {
            const __half* wp = W + (kk * 16 + (lane & 7) + ((lane >> 3) & 1) * 8) * ws
                             + nb * 16 + ((lane >> 4) << 3);
            uint32_t bh0, bh1, bh2, bh3, bl0, bl1, bl2, bl3;
            ldsm_x4_t(bh0, bh1, bh2, bh3, smem_u32(wp));
            ldsm_x4_t(bl0, bl1, bl2, bl3, smem_u32(wp + wpl));
            #pragma unroll
            for (int m = 0; m < 2; m++) {
                mma16816(acc[m][2 * nb + 0], th[m], bh0, bh1);
                mma16816(acc[m][2 * nb + 0], th[m], bl0, bl1);
                mma16816(acc[m][2 * nb + 0], tl[m], bh0, bh1);
                mma16816(acc[m][2 * nb + 1], th[m], bh2, bh3);
                mma16816(acc[m][2 * nb + 1], th[m], bl2, bl3);
                mma16816(acc[m][2 * nb + 1], tl[m], bh2, bh3);
            }
        }
    }
    convert_acc<RELU>(acc, Ah, Al);
}

// Output layer 64 -> 64 cols at noff of a 128-wide W (stride 136), fused blend:
// F <- acc*alpha + beta*(F_hi+F_lo), written back as split planes.
__device__ __forceinline__ void layer_out_blend(const uint32_t Ah[2][4][4],
                                                const uint32_t Al[2][4][4],
                                                const __half* W, int wpl, int noff,
                                                __half* F, int sf, int fpl,
                                                float alpha, float beta)
{
    const int lane = threadIdx.x & 31;
    float acc[2][8][4];
    #pragma unroll
    for (int m = 0; m < 2; m++)
        #pragma unroll
        for (int t = 0; t < 8; t++)
            #pragma unroll
            for (int j = 0; j < 4; j++) acc[m][t][j] = 0.f;

    #pragma unroll
    for (int kk = 0; kk < 4; kk++) {
        #pragma unroll
        for (int nb = 0; nb < 4; nb++) {
            const __half* wp = W + (kk * 16 + (lane & 7) + ((lane >> 3) & 1) * 8) * 136
                             + noff + nb * 16 + ((lane >> 4) << 3);
            uint32_t bh0, bh1, bh2, bh3, bl0, bl1, bl2, bl3;
            ldsm_x4_t(bh0, bh1, bh2, bh3, smem_u32(wp));
            ldsm_x4_t(bl0, bl1, bl2, bl3, smem_u32(wp + wpl));
            #pragma unroll
            for (int m = 0; m < 2; m++) {
                mma16816(acc[m][2 * nb + 0], Ah[m][kk], bh0, bh1);
                mma16816(acc[m][2 * nb + 0], Ah[m][kk], bl0, bl1);
                mma16816(acc[m][2 * nb + 0], Al[m][kk], bh0, bh1);
                mma16816(acc[m][2 * nb + 1], Ah[m][kk], bh2, bh3);
                mma16816(acc[m][2 * nb + 1], Ah[m][kk], bl2, bl3);
                mma16816(acc[m][2 * nb + 1], Al[m][kk], bh2, bh3);
            }
        }
    }

    const int g = lane >> 2, t2 = lane & 3;
    #pragma unroll
    for (int m = 0; m < 2; m++) {
        const int r0 = m * 16 + g;
        #pragma unroll
        for (int t = 0; t < 8; t++) {
            const int c0 = noff + t * 8 + t2 * 2;
            float v[4] = { acc[m][t][0], acc[m][t][1], acc[m][t][2], acc[m][t][3] };
            const int rr[4] = { r0, r0, r0 + 8, r0 + 8 };
            const int cc[4] = { c0, c0 + 1, c0, c0 + 1 };
            #pragma unroll
            for (int j = 0; j < 4; j++) {
                float fv = __half2float(F[rr[j] * sf + cc[j]])
                         + __half2float(F[rr[j] * sf + fpl + cc[j]]);
                v[j] = v[j] * alpha + beta * fv;
            }
            __half h0, l0, h1, l1, h2, l2, h3, l3;
            split2(v[0], h0, l0); split2(v[1], h1, l1);
            split2(v[2], h2, l2); split2(v[3], h3, l3);
            *(__half2*)(F + r0 * sf + c0)             = __halves2half2(h0, h1);
            *(__half2*)(F + r0 * sf + fpl + c0)       = __halves2half2(l0, l1);
            *(__half2*)(F + (r0 + 8) * sf + c0)       = __halves2half2(h2, h3);
            *(__half2*)(F + (r0 + 8) * sf + fpl + c0) = __halves2half2(l2, l3);
        }
    }
}

// ---------------------------------------------------------------------------
// Branch MLP: 256 threads = 8 warps x 32 pts = 256 pts/block.
// Activations register-resident; smem only for input staging + weights.
// ---------------------------------------------------------------------------
#define M_XPL   (256 * 72)
#define M_SMW   (256 * 72 * 2)
#define MLP64_SMEM ((M_SMW + WB_TOT) * 2)

template <int WHICH>
__global__ void __launch_bounds__(256, 1)
mlp64_tc()
{
    extern __shared__ __align__(16) __half sm[];
    const int tid = threadIdx.x;
    const size_t blockbase = (size_t)blockIdx.x * 256;

    {
        const uint4* src = (const uint4*)(WHICH == 0 ? g_wS : g_wD);
        uint4* dst = (uint4*)(sm + M_SMW);
        #pragma unroll 4
        for (int i = tid; i < WB_TOT / 8; i += 256) dst[i] = src[i];
    }
    {
        const uint4* sh = (const uint4*)((WHICH == 0 ? g_enc_s_hi : g_enc_d_hi)
                                         + blockbase * 32);
        const uint4* sl = (const uint4*)((WHICH == 0 ? g_enc_s_lo : g_enc_d_lo)
                                         + blockbase * 32);
        for (int i = tid; i < 256 * 4; i += 256) {
            int row = i >> 2, c = (i & 3) << 3;
            *(uint4*)(sm + row * 72 + c)         = sh[i];
            *(uint4*)(sm + M_XPL + row * 72 + c) = sl[i];
        }
    }
    __syncthreads();

    const int w = tid >> 5;
    const int lane = tid & 31;
    __half* X = sm + w * 32 * 72;
    const __half* W = sm + M_SMW;

    uint32_t Ah[2][4][4], Al[2][4][4];

    // Layer 1: 32 -> 64, A from staged smem
    layer_smemA<2, true>(X, 72, M_XPL, W + WB_IN, 72, 32 * 72, Ah, Al);
    // Layers 2-5: register-resident
    layer_reg<4, true >(Ah, Al, W + WB_H0,  72, 64 * 72);
    layer_reg<4, true >(Ah, Al, W + WB_H1,  72, 64 * 72);
    layer_reg<4, true >(Ah, Al, W + WB_H2,  72, 64 * 72);
    layer_reg<4, false>(Ah, Al, W + WB_OUT, 72, 64 * 72);

    // Stage fragments to smem (warp-private slice), then coalesced g_feat store
    {
        const int g = lane >> 2, t2 = lane & 3;
        #pragma unroll
        for (int m = 0; m < 2; m++)
            #pragma unroll
            for (int j = 0; j < 4; j++) {
                const int r = m * 16 + g, c = j * 16 + t2 * 2;
                *(uint32_t*)(X + r * 72 + c)               = Ah[m][j][0];
                *(uint32_t*)(X + (r + 8) * 72 + c)         = Ah[m][j][1];
                *(uint32_t*)(X + r * 72 + c + 8)           = Ah[m][j][2];
                *(uint32_t*)(X + (r + 8) * 72 + c + 8)     = Ah[m][j][3];
                *(uint32_t*)(X + M_XPL + r * 72 + c)       = Al[m][j][0];
                *(uint32_t*)(X + M_XPL + (r + 8) * 72 + c) = Al[m][j][1];
                *(uint32_t*)(X + M_XPL + r * 72 + c + 8)   = Al[m][j][2];
                *(uint32_t*)(X + M_XPL + (r + 8) * 72 + c + 8) = Al[m][j][3];
            }
    }
    __syncwarp();

    for (int i = lane; i < 32 * 8; i += 32) {
        int row = i >> 3, c = (i & 7) << 3;
        size_t pt = blockbase + w * 32 + row;
        *(uint4*)(g_feat_hi + pt * 128 + WHICH * 64 + c) = *(const uint4*)(X + row * 72 + c);
        *(uint4*)(g_feat_lo + pt * 128 + WHICH * 64 + c) = *(const uint4*)(X + M_XPL + row * 72 + c);
    }
}

// ---------------------------------------------------------------------------
// Merged head: feat128 -> 64 -> 64 -> 128 (+blend) -> 64 -> 64 -> 1
// 128 threads = 4 warps x 32 pts = 128 pts/block.  F stays in smem.
// ---------------------------------------------------------------------------
#define HF_PL  (128 * 136)
#define HW1    (HF_PL * 2)
#define HW2    (HW1 + H1_TOT)
#define HWO    (HW2 + H2_TOT)
#define HEAD_SMEM ((HWO + 128) * 2)

__global__ void __launch_bounds__(128, 1)
head_tc(const float* __restrict__ alpha_p,
        const float* __restrict__ w2_out, float* __restrict__ out)
{
    extern __shared__ __align__(16) __half sm[];
    const int tid = threadIdx.x;
    const size_t blockbase = (size_t)blockIdx.x * 128;
    float* wo = (float*)(sm + HWO);

    {
        const uint4* s1 = (const uint4*)g_wH1;
        uint4* d1 = (uint4*)(sm + HW1);
        #pragma unroll 4
        for (int i = tid; i < H1_TOT / 8; i += 128) d1[i] = s1[i];
        const uint4* s2 = (const uint4*)g_wH2;
        uint4* d2 = (uint4*)(sm + HW2);
        #pragma unroll 4
        for (int i = tid; i < H2_TOT / 8; i += 128) d2[i] = s2[i];
        for (int i = tid; i < 64; i += 128) wo[i] = w2_out[i];
    }
    {
        const uint4* fh = (const uint4*)(g_feat_hi + blockbase * 128);
        const uint4* fl = (const uint4*)(g_feat_lo + blockbase * 128);
        for (int i = tid; i < 128 * 16; i += 128) {
            int row = i >> 4, c = (i & 15) << 3;
            *(uint4*)(sm + row * 136 + c)         = fh[i];
            *(uint4*)(sm + HF_PL + row * 136 + c) = fl[i];
        }
    }
    __syncthreads();

    const int w = tid >> 5;
    const int lane = tid & 31;
    __half* F = sm + w * 32 * 136;

    const float alpha = __ldg(alpha_p);
    const float beta  = 1.f - alpha;

    uint32_t Ah[2][4][4], Al[2][4][4];

    // mlp1: 128 -> 64 -> 64 -> 128 with fused blend into F
    layer_smemA<8, true>(F, 136, HF_PL, sm + HW1 + H1_IN, 72, 128 * 72, Ah, Al);
    layer_reg<4, true>(Ah, Al, sm + HW1 + H1_H, 72, 64 * 72);
    layer_out_blend(Ah, Al, sm + HW1 + H1_OUT, 64 * 136, 0,  F, 136, HF_PL, alpha, beta);
    layer_out_blend(Ah, Al, sm + HW1 + H1_OUT, 64 * 136, 64, F, 136, HF_PL, alpha, beta);
    __syncwarp();

    // mlp2: blended 128 -> 64 -> 64
    layer_smemA<8, true>(F, 136, HF_PL, sm + HW2 + H2_IN, 72, 128 * 72, Ah, Al);
    layer_reg<4, true>(Ah, Al, sm + HW2 + H2_H, 72, 64 * 72);

    // final 64 -> 1 from register fragments (fp32)
    const int g = lane >> 2, t2 = lane & 3;
    #pragma unroll
    for (int m = 0; m < 2; m++) {
        float sg = 0.f, sg8 = 0.f;
        #pragma unroll
        for (int j = 0; j < 4; j++)
            #pragma unroll
            for (int q = 0; q < 4; q++) {
                __half2 hv = *reinterpret_cast<__half2*>(&Ah[m][j][q]);
                __half2 lv = *reinterpret_cast<__half2*>(&Al[m][j][q]);
                float2 vh = __half22float2(hv);
                float2 vl = __half22float2(lv);
                int c = j * 16 + ((q >> 1) << 3) + t2 * 2;
                float d = fmaf(vh.x + vl.x, wo[c], (vh.y + vl.y) * wo[c + 1]);
                if ((q & 1) == 0) sg += d; else sg8 += d;
            }
        sg  += __shfl_xor_sync(0xffffffffu, sg, 1);
        sg  += __shfl_xor_sync(0xffffffffu, sg, 2);
        sg8 += __shfl_xor_sync(0xffffffffu, sg8, 1);
        sg8 += __shfl_xor_sync(0xffffffffu, sg8, 2);
        if (t2 == 0) {
            out[blockbase + w * 32 + m * 16 + g]     = sg;
            out[blockbase + w * 32 + m * 16 + g + 8] = sg8;
        }
    }
}

// ---------------------------------------------------------------------------
// Launch (strictly serial — R5 showed L1-bound kernels must not overlap)
// ---------------------------------------------------------------------------
extern "C" void kernel_launch(void* const* d_in, const int* in_sizes, int n_in,
                              void* d_out, int out_size)
{
    const float* x       = (const float*)d_in[0];
    const float* t       = (const float*)d_in[1];
    const float* alpha   = (const float*)d_in[2];
    const float* table_s = (const float*)d_in[3];
    const float* ws_in   = (const float*)d_in[4];
    const float* ws_hid  = (const float*)d_in[5];
    const float* ws_out  = (const float*)d_in[6];
    const float* table_d = (const float*)d_in[7];
    const float* wd_in   = (const float*)d_in[8];
    const float* wd_hid  = (const float*)d_in[9];
    const float* wd_out  = (const float*)d_in[10];
    const float* w1_in   = (const float*)d_in[11];
    const float* w1_hid  = (const float*)d_in[12];
    const float* w1_out  = (const float*)d_in[13];
    const float* w2_in   = (const float*)d_in[14];
    const float* w2_hid  = (const float*)d_in[15];
    const float* w2_out  = (const float*)d_in[16];
    float* out = (float*)d_out;

    cudaFuncSetAttribute(mlp64_tc<0>, cudaFuncAttributeMaxDynamicSharedMemorySize, MLP64_SMEM);
    cudaFuncSetAttribute(mlp64_tc<1>, cudaFuncAttributeMaxDynamicSharedMemorySize, MLP64_SMEM);
    cudaFuncSetAttribute(head_tc,     cudaFuncAttributeMaxDynamicSharedMemorySize, HEAD_SMEM);

    const int nblkENC = NPTS / 256;
    const int nblkMLP = NPTS / 256;
    const int nblkHD  = NPTS / 128;

    prep_weights<<<64, 256>>>(ws_in, ws_hid, ws_out, wd_in, wd_hid, wd_out,
                              w1_in, w1_hid, w1_out, w2_in, w2_hid);

    encode_kernel<3, 0><<<nblkENC, 256>>>(x, nullptr, table_s);
    encode_kernel<4, 1><<<nblkENC, 256>>>(x, t, table_d);

    mlp64_tc<0><<<nblkMLP, 256, MLP64_SMEM>>>();
    mlp64_tc<1><<<nblkMLP, 256, MLP64_SMEM>>>();

    head_tc<<<nblkHD, 128, HEAD_SMEM>>>(alpha, w2_out, out);
}

// round 8
// speedup vs baseline: 1.4766x; 1.1912x over previous
#include <cuda_runtime.h>
#include <cuda_fp16.h>
#include <cstdint>

// ---------------------------------------------------------------------------
// Problem constants
// ---------------------------------------------------------------------------
#define NPTS   524288
#define LVLS   16
#define TSIZE  524288u
#define TMASK  (TSIZE - 1u)

__constant__ float c_res[LVLS] = {
    16.f, 24.f, 36.f, 54.f, 81.f, 121.f, 182.f, 273.f,
    410.f, 615.f, 922.f, 1383.f, 2075.f, 3113.f, 4670.f, 7006.f
};

// ---------------------------------------------------------------------------
// Scratch (device globals; no runtime allocation)
// ---------------------------------------------------------------------------
__device__ __align__(16) __half g_enc_s_hi[(size_t)NPTS * 32];
__device__ __align__(16) __half g_enc_s_lo[(size_t)NPTS * 32];
__device__ __align__(16) __half g_enc_d_hi[(size_t)NPTS * 32];
__device__ __align__(16) __half g_enc_d_lo[(size_t)NPTS * 32];
__device__ __align__(16) __half g_feat_hi [(size_t)NPTS * 128];
__device__ __align__(16) __half g_feat_lo [(size_t)NPTS * 128];

// Pre-split weight blobs (hi plane, lo plane at +rows*stride), stride 72/136
#define WB_IN   0
#define WB_H0   4608
#define WB_H1   13824
#define WB_H2   23040
#define WB_OUT  32256
#define WB_TOT  41472
__device__ __align__(16) __half g_wS[WB_TOT];
__device__ __align__(16) __half g_wD[WB_TOT];
#define H1_IN   0
#define H1_H    18432
#define H1_OUT  27648
#define H1_TOT  45056
__device__ __align__(16) __half g_wH1[H1_TOT];
#define H2_IN   0
#define H2_H    18432
#define H2_TOT  27648
__device__ __align__(16) __half g_wH2[H2_TOT];

// ---------------------------------------------------------------------------
__device__ __forceinline__ void split2(float x, __half& h, __half& l) {
    h = __float2half_rn(x);
    l = __float2half_rn(x - __half2float(h));
}

__device__ __forceinline__ uint32_t pack2(__half a, __half b) {
    __half2 v = __halves2half2(a, b);
    return *reinterpret_cast<uint32_t*>(&v);
}

__device__ __forceinline__ void conv_w(__half* dst, const float* __restrict__ src,
                                       int K, int N, int ws, int t0, int nt)
{
    const int tot = K * N / 2;
    const int pl  = K * ws;
    const float2* s2 = (const float2*)src;
    for (int i = t0; i < tot; i += nt) {
        int r = (2 * i) / N, c = (2 * i) % N;
        float2 v = s2[i];
        __half hx, lx, hy, ly;
        split2(v.x, hx, lx);
        split2(v.y, hy, ly);
        *(__half2*)(dst + r * ws + c)      = __halves2half2(hx, hy);
        *(__half2*)(dst + r * ws + pl + c) = __halves2half2(lx, ly);
    }
}

__global__ void __launch_bounds__(256)
prep_weights(const float* __restrict__ ws_in, const float* __restrict__ ws_hid,
             const float* __restrict__ ws_out,
             const float* __restrict__ wd_in, const float* __restrict__ wd_hid,
             const float* __restrict__ wd_out,
             const float* __restrict__ w1_in, const float* __restrict__ w1_hid,
             const float* __restrict__ w1_out,
             const float* __restrict__ w2_in, const float* __restrict__ w2_hid)
{
    const int t0 = blockIdx.x * 256 + threadIdx.x;
    const int nt = gridDim.x * 256;
    conv_w(g_wS + WB_IN,  ws_in,         32, 64, 72, t0, nt);
    conv_w(g_wS + WB_H0,  ws_hid + 0,    64, 64, 72, t0, nt);
    conv_w(g_wS + WB_H1,  ws_hid + 4096, 64, 64, 72, t0, nt);
    conv_w(g_wS + WB_H2,  ws_hid + 8192, 64, 64, 72, t0, nt);
    conv_w(g_wS + WB_OUT, ws_out,        64, 64, 72, t0, nt);
    conv_w(g_wD + WB_IN,  wd_in,         32, 64, 72, t0, nt);
    conv_w(g_wD + WB_H0,  wd_hid + 0,    64, 64, 72, t0, nt);
    conv_w(g_wD + WB_H1,  wd_hid + 4096, 64, 64, 72, t0, nt);
    conv_w(g_wD + WB_H2,  wd_hid + 8192, 64, 64, 72, t0, nt);
    conv_w(g_wD + WB_OUT, wd_out,        64, 64, 72, t0, nt);
    conv_w(g_wH1 + H1_IN,  w1_in,  128, 64,  72,  t0, nt);
    conv_w(g_wH1 + H1_H,   w1_hid, 64,  64,  72,  t0, nt);
    conv_w(g_wH1 + H1_OUT, w1_out, 64,  128, 136, t0, nt);
    conv_w(g_wH2 + H2_IN,  w2_in,  128, 64,  72,  t0, nt);
    conv_w(g_wH2 + H2_H,   w2_hid, 64,  64,  72,  t0, nt);
}

// ---------------------------------------------------------------------------
// Hash-grid encode (one point per thread, all 16 levels) — at gather floor.
// ---------------------------------------------------------------------------
template <int D, int WHICH>
__global__ void __launch_bounds__(256)
encode_kernel(const float* __restrict__ x,
              const float* __restrict__ tptr,
              const float* __restrict__ table)
{
    const int n = blockIdx.x * 256 + threadIdx.x;

    float p[4];
    p[0] = x[3 * n + 0];
    p[1] = x[3 * n + 1];
    p[2] = x[3 * n + 2];
    if (D == 4) p[3] = __ldg(tptr);

    __half2 ehi[16], elo[16];

    #pragma unroll
    for (int l = 0; l < LVLS; l++) {
        const float res = c_res[l];
        uint32_t h[4][2];
        float    w[4][2];
        #pragma unroll
        for (int d = 0; d < D; d++) {
            const uint32_t pr = (d == 0) ? 1u
                              : (d == 1) ? 2654435761u
                              : (d == 2) ? 805459861u
                                         : 3674653429u;
            float pos = p[d] * res;
            float p0f = floorf(pos);
            float fr  = pos - p0f;
            uint32_t p0 = (uint32_t)p0f;
            h[d][0] = p0 * pr;
            h[d][1] = (p0 + 1u) * pr;
            w[d][0] = 1.f - fr;
            w[d][1] = fr;
        }

        const float2* tl = (const float2*)table + (size_t)l * TSIZE;
        float f0 = 0.f, f1 = 0.f;
        #pragma unroll
        for (int c = 0; c < (1 << D); c++) {
            uint32_t hh = h[0][c & 1] ^ h[1][(c >> 1) & 1] ^ h[2][(c >> 2) & 1];
            float    ww = w[0][c & 1] * w[1][(c >> 1) & 1] * w[2][(c >> 2) & 1];
            if (D == 4) {
                hh ^= h[3][(c >> 3) & 1];
                ww *= w[3][(c >> 3) & 1];
            }
            float2 f = __ldg(tl + (hh & TMASK));
            f0 = fmaf(ww, f.x, f0);
            f1 = fmaf(ww, f.y, f1);
        }
        __half h0, l0, h1, l1;
        split2(f0, h0, l0);
        split2(f1, h1, l1);
        ehi[l] = __halves2half2(h0, h1);
        elo[l] = __halves2half2(l0, l1);
    }

    __half* dh = (WHICH == 0 ? g_enc_s_hi : g_enc_d_hi) + (size_t)n * 32;
    __half* dl = (WHICH == 0 ? g_enc_s_lo : g_enc_d_lo) + (size_t)n * 32;
    #pragma unroll
    for (int i = 0; i < 4; i++) ((uint4*)dh)[i] = ((const uint4*)ehi)[i];
    #pragma unroll
    for (int i = 0; i < 4; i++) ((uint4*)dl)[i] = ((const uint4*)elo)[i];
}

// ---------------------------------------------------------------------------
// Tensor-core primitives
// ---------------------------------------------------------------------------
__device__ __forceinline__ uint32_t smem_u32(const void* p) {
    return (uint32_t)__cvta_generic_to_shared(p);
}

__device__ __forceinline__ void ldsm_x4(uint32_t& r0, uint32_t& r1,
                                        uint32_t& r2, uint32_t& r3, uint32_t a) {
    asm volatile("ldmatrix.sync.aligned.m8n8.x4.shared.b16 {%0,%1,%2,%3}, [%4];"
                 : "=r"(r0), "=r"(r1), "=r"(r2), "=r"(r3) : "r"(a));
}

__device__ __forceinline__ void ldsm_x4_t(uint32_t& r0, uint32_t& r1,
                                          uint32_t& r2, uint32_t& r3, uint32_t a) {
    asm volatile("ldmatrix.sync.aligned.m8n8.x4.trans.shared.b16 {%0,%1,%2,%3}, [%4];"
                 : "=r"(r0), "=r"(r1), "=r"(r2), "=r"(r3) : "r"(a));
}

__device__ __forceinline__ void mma16816(float* c, const uint32_t* a,
                                         uint32_t b0, uint32_t b1) {
    asm volatile(
        "mma.sync.aligned.m16n8k16.row.col.f32.f16.f16.f32 "
        "{%0,%1,%2,%3}, {%4,%5,%6,%7}, {%8,%9}, {%0,%1,%2,%3};"
        : "+f"(c[0]), "+f"(c[1]), "+f"(c[2]), "+f"(c[3])
        : "r"(a[0]), "r"(a[1]), "r"(a[2]), "r"(a[3]), "r"(b0), "r"(b1));
}

// ---------------------------------------------------------------------------
// Register-resident split-fp16 layers (MT M-tiles of 16 rows per warp).
// Identity: C-fragments of n-tile pair {2j,2j+1} == A-fragments of k-tile j.
// ---------------------------------------------------------------------------
template <int MT, bool RELU>
__device__ __forceinline__ void convert_acc(float (*acc)[8][4],
                                            uint32_t (*Ah)[4][4],
                                            uint32_t (*Al)[4][4])
{
    #pragma unroll
    for (int m = 0; m < MT; m++)
        #pragma unroll
        for (int j = 0; j < 4; j++)
            #pragma unroll
            for (int q = 0; q < 4; q++) {
                float v0 = acc[m][2 * j + (q >> 1)][(q & 1) * 2 + 0];
                float v1 = acc[m][2 * j + (q >> 1)][(q & 1) * 2 + 1];
                if (RELU) { v0 = fmaxf(v0, 0.f); v1 = fmaxf(v1, 0.f); }
                __half h0, l0, h1, l1;
                split2(v0, h0, l0);
                split2(v1, h1, l1);
                Ah[m][j][q] = pack2(h0, h1);
                Al[m][j][q] = pack2(l0, l1);
            }
}

template <int MT, int KT, bool RELU>
__device__ __forceinline__ void layer_reg(uint32_t (*Ah)[4][4],
                                          uint32_t (*Al)[4][4],
                                          const __half* W, int ws, int wpl)
{
    const int lane = threadIdx.x & 31;
    float acc[MT][8][4];
    #pragma unroll
    for (int m = 0; m < MT; m++)
        #pragma unroll
        for (int t = 0; t < 8; t++)
            #pragma unroll
            for (int j = 0; j < 4; j++) acc[m][t][j] = 0.f;

    #pragma unroll
    for (int kk = 0; kk < KT; kk++) {
        #pragma unroll
        for (int nb = 0; nb < 4; nb++) {
            const __half* wp = W + (kk * 16 + (lane & 7) + ((lane >> 3) & 1) * 8) * ws
                             + nb * 16 + ((lane >> 4) << 3);
            uint32_t bh0, bh1, bh2, bh3, bl0, bl1, bl2, bl3;
            ldsm_x4_t(bh0, bh1, bh2, bh3, smem_u32(wp));
            ldsm_x4_t(bl0, bl1, bl2, bl3, smem_u32(wp + wpl));
            #pragma unroll
            for (int m = 0; m < MT; m++) {
                mma16816(acc[m][2 * nb + 0], Ah[m][kk], bh0, bh1);
                mma16816(acc[m][2 * nb + 0], Ah[m][kk], bl0, bl1);
                mma16816(acc[m][2 * nb + 0], Al[m][kk], bh0, bh1);
                mma16816(acc[m][2 * nb + 1], Ah[m][kk], bh2, bh3);
                mma16816(acc[m][2 * nb + 1], Ah[m][kk], bl2, bl3);
                mma16816(acc[m][2 * nb + 1], Al[m][kk], bh2, bh3);
            }
        }
    }
    convert_acc<MT, RELU>(acc, Ah, Al);
}

template <int MT, int KT, bool RELU>
__device__ __forceinline__ void layer_smemA(const __half* A, int sa, int apl,
                                            const __half* W, int ws, int wpl,
                                            uint32_t (*Ah)[4][4],
                                            uint32_t (*Al)[4][4])
{
    const int lane = threadIdx.x & 31;
    float acc[MT][8][4];
    #pragma unroll
    for (int m = 0; m < MT; m++)
        #pragma unroll
        for (int t = 0; t < 8; t++)
            #pragma unroll
            for (int j = 0; j < 4; j++) acc[m][t][j] = 0.f;

    #pragma unroll
    for (int kk = 0; kk < KT; kk++) {
        uint32_t th[MT][4], tl[MT][4];
        #pragma unroll
        for (int m = 0; m < MT; m++) {
            const __half* ap = A + (m * 16 + (lane & 15)) * sa + kk * 16
                             + ((lane >> 4) << 3);
            ldsm_x4(th[m][0], th[m][1], th[m][2], th[m][3], smem_u32(ap));
            ldsm_x4(tl[m][0], tl[m][1], tl[m][2], tl[m][3], smem_u32(ap + apl));
        }
        #pragma unroll
        for (int nb = 0; nb < 4; nb++) {
            const __half* wp = W + (kk * 16 + (lane & 7) + ((lane >> 3) & 1) * 8) * ws
                             + nb * 16 + ((lane >> 4) << 3);
            uint32_t bh0, bh1, bh2, bh3, bl0, bl1, bl2, bl3;
            ldsm_x4_t(bh0, bh1, bh2, bh3, smem_u32(wp));
            ldsm_x4_t(bl0, bl1, bl2, bl3, smem_u32(wp + wpl));
            #pragma unroll
            for (int m = 0; m < MT; m++) {
                mma16816(acc[m][2 * nb + 0], th[m], bh0, bh1);
                mma16816(acc[m][2 * nb + 0], th[m], bl0, bl1);
                mma16816(acc[m][2 * nb + 0], tl[m], bh0, bh1);
                mma16816(acc[m][2 * nb + 1], th[m], bh2, bh3);
                mma16816(acc[m][2 * nb + 1], th[m], bl2, bl3);
                mma16816(acc[m][2 * nb + 1], tl[m], bh2, bh3);
            }
        }
    }
    convert_acc<MT, RELU>(acc, Ah, Al);
}

// Output layer 64 -> 64 cols at noff of a 128-wide W (stride 136), fused blend.
template <int MT>
__device__ __forceinline__ void layer_out_blend(const uint32_t (*Ah)[4][4],
                                                const uint32_t (*Al)[4][4],
                                                const __half* W, int wpl, int noff,
                                                __half* F, int sf, int fpl,
                                                float alpha, float beta)
{
    const int lane = threadIdx.x & 31;
    float acc[MT][8][4];
    #pragma unroll
    for (int m = 0; m < MT; m++)
        #pragma unroll
        for (int t = 0; t < 8; t++)
            #pragma unroll
            for (int j = 0; j < 4; j++) acc[m][t][j] = 0.f;

    #pragma unroll
    for (int kk = 0; kk < 4; kk++) {
        #pragma unroll
        for (int nb = 0; nb < 4; nb++) {
            const __half* wp = W + (kk * 16 + (lane & 7) + ((lane >> 3) & 1) * 8) * 136
                             + noff + nb * 16 + ((lane >> 4) << 3);
            uint32_t bh0, bh1, bh2, bh3, bl0, bl1, bl2, bl3;
            ldsm_x4_t(bh0, bh1, bh2, bh3, smem_u32(wp));
            ldsm_x4_t(bl0, bl1, bl2, bl3, smem_u32(wp + wpl));
            #pragma unroll
            for (int m = 0; m < MT; m++) {
                mma16816(acc[m][2 * nb + 0], Ah[m][kk], bh0, bh1);
                mma16816(acc[m][2 * nb + 0], Ah[m][kk], bl0, bl1);
                mma16816(acc[m][2 * nb + 0], Al[m][kk], bh0, bh1);
                mma16816(acc[m][2 * nb + 1], Ah[m][kk], bh2, bh3);
                mma16816(acc[m][2 * nb + 1], Ah[m][kk], bl2, bl3);
                mma16816(acc[m][2 * nb + 1], Al[m][kk], bh2, bh3);
            }
        }
    }

    const int g = lane >> 2, t2 = lane & 3;
    #pragma unroll
    for (int m = 0; m < MT; m++) {
        const int r0 = m * 16 + g;
        #pragma unroll
        for (int t = 0; t < 8; t++) {
            const int c0 = noff + t * 8 + t2 * 2;
            float v[4] = { acc[m][t][0], acc[m][t][1], acc[m][t][2], acc[m][t][3] };
            const int rr[4] = { r0, r0, r0 + 8, r0 + 8 };
            const int cc[4] = { c0, c0 + 1, c0, c0 + 1 };
            #pragma unroll
            for (int j = 0; j < 4; j++) {
                float fv = __half2float(F[rr[j] * sf + cc[j]])
                         + __half2float(F[rr[j] * sf + fpl + cc[j]]);
                v[j] = v[j] * alpha + beta * fv;
            }
            __half h0, l0, h1, l1, h2, l2, h3, l3;
            split2(v[0], h0, l0); split2(v[1], h1, l1);
            split2(v[2], h2, l2); split2(v[3], h3, l3);
            *(__half2*)(F + r0 * sf + c0)             = __halves2half2(h0, h1);
            *(__half2*)(F + r0 * sf + fpl + c0)       = __halves2half2(l0, l1);
            *(__half2*)(F + (r0 + 8) * sf + c0)       = __halves2half2(h2, h3);
            *(__half2*)(F + (r0 + 8) * sf + fpl + c0) = __halves2half2(l2, l3);
        }
    }
}

// ---------------------------------------------------------------------------
// Branch MLP: 512 threads = 16 warps x 16 pts = 256 pts/block, MT=1.
// Input staged at stride 40 (conflict-free 80B rows); output direct to g_feat.
// ---------------------------------------------------------------------------
#define M_XS    40
#define M_XPL   (256 * M_XS)
#define M_SMW   (256 * M_XS * 2)
#define MLP64_SMEM ((M_SMW + WB_TOT) * 2)

template <int WHICH>
__global__ void __launch_bounds__(512, 1)
mlp64_tc()
{
    extern __shared__ __align__(16) __half sm[];
    const int tid = threadIdx.x;
    const size_t blockbase = (size_t)blockIdx.x * 256;

    {
        const uint4* src = (const uint4*)(WHICH == 0 ? g_wS : g_wD);
        uint4* dst = (uint4*)(sm + M_SMW);
        #pragma unroll 4
        for (int i = tid; i < WB_TOT / 8; i += 512) dst[i] = src[i];
    }
    {
        const uint4* sh = (const uint4*)((WHICH == 0 ? g_enc_s_hi : g_enc_d_hi)
                                         + blockbase * 32);
        const uint4* sl = (const uint4*)((WHICH == 0 ? g_enc_s_lo : g_enc_d_lo)
                                         + blockbase * 32);
        for (int i = tid; i < 256 * 4; i += 512) {
            int row = i >> 2, c = (i & 3) << 3;
            *(uint4*)(sm + row * M_XS + c)         = sh[i];
            *(uint4*)(sm + M_XPL + row * M_XS + c) = sl[i];
        }
    }
    __syncthreads();

    const int w = tid >> 5;
    const int lane = tid & 31;
    __half* X = sm + w * 16 * M_XS;
    const __half* W = sm + M_SMW;

    uint32_t Ah[1][4][4], Al[1][4][4];

    layer_smemA<1, 2, true>(X, M_XS, M_XPL, W + WB_IN, 72, 32 * 72, Ah, Al);
    layer_reg<1, 4, true >(Ah, Al, W + WB_H0,  72, 64 * 72);
    layer_reg<1, 4, true >(Ah, Al, W + WB_H1,  72, 64 * 72);
    layer_reg<1, 4, true >(Ah, Al, W + WB_H2,  72, 64 * 72);
    layer_reg<1, 4, false>(Ah, Al, W + WB_OUT, 72, 64 * 72);

    // Direct fragment store to g_feat (no smem staging)
    {
        const int g = lane >> 2, t2 = lane & 3;
        const size_t pt0 = blockbase + w * 16 + g;
        #pragma unroll
        for (int j = 0; j < 4; j++) {
            const int c = WHICH * 64 + j * 16 + t2 * 2;
            *(uint32_t*)(g_feat_hi + pt0 * 128 + c)           = Ah[0][j][0];
            *(uint32_t*)(g_feat_hi + (pt0 + 8) * 128 + c)     = Ah[0][j][1];
            *(uint32_t*)(g_feat_hi + pt0 * 128 + c + 8)       = Ah[0][j][2];
            *(uint32_t*)(g_feat_hi + (pt0 + 8) * 128 + c + 8) = Ah[0][j][3];
            *(uint32_t*)(g_feat_lo + pt0 * 128 + c)           = Al[0][j][0];
            *(uint32_t*)(g_feat_lo + (pt0 + 8) * 128 + c)     = Al[0][j][1];
            *(uint32_t*)(g_feat_lo + pt0 * 128 + c + 8)       = Al[0][j][2];
            *(uint32_t*)(g_feat_lo + (pt0 + 8) * 128 + c + 8) = Al[0][j][3];
        }
    }
}

// ---------------------------------------------------------------------------
// Merged head: 256 threads = 8 warps x 16 pts = 128 pts/block, MT=1.
// feat128 -> 64 -> 64 -> 128 (+blend) -> 64 -> 64 -> 1.  F stays in smem.
// ---------------------------------------------------------------------------
#define HF_PL  (128 * 136)
#define HW1    (HF_PL * 2)
#define HW2    (HW1 + H1_TOT)
#define HWO    (HW2 + H2_TOT)
#define HEAD_SMEM ((HWO + 128) * 2)

__global__ void __launch_bounds__(256, 1)
head_tc(const float* __restrict__ alpha_p,
        const float* __restrict__ w2_out, float* __restrict__ out)
{
    extern __shared__ __align__(16) __half sm[];
    const int tid = threadIdx.x;
    const size_t blockbase = (size_t)blockIdx.x * 128;
    float* wo = (float*)(sm + HWO);

    {
        const uint4* s1 = (const uint4*)g_wH1;
        uint4* d1 = (uint4*)(sm + HW1);
        #pragma unroll 4
        for (int i = tid; i < H1_TOT / 8; i += 256) d1[i] = s1[i];
        const uint4* s2 = (const uint4*)g_wH2;
        uint4* d2 = (uint4*)(sm + HW2);
        #pragma unroll 4
        for (int i = tid; i < H2_TOT / 8; i += 256) d2[i] = s2[i];
        for (int i = tid; i < 64; i += 256) wo[i] = w2_out[i];
    }
    {
        const uint4* fh = (const uint4*)(g_feat_hi + blockbase * 128);
        const uint4* fl = (const uint4*)(g_feat_lo + blockbase * 128);
        for (int i = tid; i < 128 * 16; i += 256) {
            int row = i >> 4, c = (i & 15) << 3;
            *(uint4*)(sm + row * 136 + c)         = fh[i];
            *(uint4*)(sm + HF_PL + row * 136 + c) = fl[i];
        }
    }
    __syncthreads();

    const int w = tid >> 5;
    const int lane = tid & 31;
    __half* F = sm + w * 16 * 136;

    const float alpha = __ldg(alpha_p);
    const float beta  = 1.f - alpha;

    uint32_t Ah[1][4][4], Al[1][4][4];

    // mlp1: 128 -> 64 -> 64 -> 128 with fused blend into F
    layer_smemA<1, 8, true>(F, 136, HF_PL, sm + HW1 + H1_IN, 72, 128 * 72, Ah, Al);
    layer_reg<1, 4, true>(Ah, Al, sm + HW1 + H1_H, 72, 64 * 72);
    layer_out_blend<1>(Ah, Al, sm + HW1 + H1_OUT, 64 * 136, 0,  F, 136, HF_PL, alpha, beta);
    layer_out_blend<1>(Ah, Al, sm + HW1 + H1_OUT, 64 * 136, 64, F, 136, HF_PL, alpha, beta);
    __syncwarp();

    // mlp2: blended 128 -> 64 -> 64
    layer_smemA<1, 8, true>(F, 136, HF_PL, sm + HW2 + H2_IN, 72, 128 * 72, Ah, Al);
    layer_reg<1, 4, true>(Ah, Al, sm + HW2 + H2_H, 72, 64 * 72);

    // final 64 -> 1 from register fragments (fp32)
    const int g = lane >> 2, t2 = lane & 3;
    {
        float sg = 0.f, sg8 = 0.f;
        #pragma unroll
        for (int j = 0; j < 4; j++)
            #pragma unroll
            for (int q = 0; q < 4; q++) {
                __half2 hv = *reinterpret_cast<__half2*>(&Ah[0][j][q]);
                __half2 lv = *reinterpret_cast<__half2*>(&Al[0][j][q]);
                float2 vh = __half22float2(hv);
                float2 vl = __half22float2(lv);
                int c = j * 16 + ((q >> 1) << 3) + t2 * 2;
                float d = fmaf(vh.x + vl.x, wo[c], (vh.y + vl.y) * wo[c + 1]);
                if ((q & 1) == 0) sg += d; else sg8 += d;
            }
        sg  += __shfl_xor_sync(0xffffffffu, sg, 1);
        sg  += __shfl_xor_sync(0xffffffffu, sg, 2);
        sg8 += __shfl_xor_sync(0xffffffffu, sg8, 1);
        sg8 += __shfl_xor_sync(0xffffffffu, sg8, 2);
        if (t2 == 0) {
            out[blockbase + w * 16 + g]     = sg;
            out[blockbase + w * 16 + g + 8] = sg8;
        }
    }
}

// ---------------------------------------------------------------------------
// Launch (strictly serial — R5 showed L1-bound kernels must not overlap)
// ---------------------------------------------------------------------------
extern "C" void kernel_launch(void* const* d_in, const int* in_sizes, int n_in,
                              void* d_out, int out_size)
{
    const float* x       = (const float*)d_in[0];
    const float* t       = (const float*)d_in[1];
    const float* alpha   = (const float*)d_in[2];
    const float* table_s = (const float*)d_in[3];
    const float* ws_in   = (const float*)d_in[4];
    const float* ws_hid  = (const float*)d_in[5];
    const float* ws_out  = (const float*)d_in[6];
    const float* table_d = (const float*)d_in[7];
    const float* wd_in   = (const float*)d_in[8];
    const float* wd_hid  = (const float*)d_in[9];
    const float* wd_out  = (const float*)d_in[10];
    const float* w1_in   = (const float*)d_in[11];
    const float* w1_hid  = (const float*)d_in[12];
    const float* w1_out  = (const float*)d_in[13];
    const float* w2_in   = (const float*)d_in[14];
    const float* w2_hid  = (const float*)d_in[15];
    const float* w2_out  = (const float*)d_in[16];
    float* out = (float*)d_out;

    cudaFuncSetAttribute(mlp64_tc<0>, cudaFuncAttributeMaxDynamicSharedMemorySize, MLP64_SMEM);
    cudaFuncSetAttribute(mlp64_tc<1>, cudaFuncAttributeMaxDynamicSharedMemorySize, MLP64_SMEM);
    cudaFuncSetAttribute(head_tc,     cudaFuncAttributeMaxDynamicSharedMemorySize, HEAD_SMEM);

    const int nblkENC = NPTS / 256;
    const int nblkMLP = NPTS / 256;
    const int nblkHD  = NPTS / 128;

    prep_weights<<<64, 256>>>(ws_in, ws_hid, ws_out, wd_in, wd_hid, wd_out,
                              w1_in, w1_hid, w1_out, w2_in, w2_hid);

    encode_kernel<3, 0><<<nblkENC, 256>>>(x, nullptr, table_s);
    encode_kernel<4, 1><<<nblkENC, 256>>>(x, t, table_d);

    mlp64_tc<0><<<nblkMLP, 512, MLP64_SMEM>>>();
    mlp64_tc<1><<<nblkMLP, 512, MLP64_SMEM>>>();

    head_tc<<<nblkHD, 256, HEAD_SMEM>>>(alpha, w2_out, out);
}